// round 11
// baseline (speedup 1.0000x reference)
#include <cuda_runtime.h>
#include <cuda_bf16.h>
#include <cstdint>

// ---------------- problem constants ----------------
#define B_    8
#define TTXT  40
#define SIMG  1024
#define NTOK  1064
#define CDIM  768
#define H_    12
#define HD    64
#define MROWS (B_*NTOK)       // 8512
#define MPAD  8576            // 67*128
#define K3    (3*CDIM)        // 2304
#define NQKV  (3*CDIM)        // 2304

// ---------------- device scratch (referenced ONLY from device code) ----------------
__device__ float g_q [B_*H_*NTOK*HD];
__device__ float g_k [B_*H_*NTOK*HD];
__device__ float g_v [B_*H_*NTOK*HD];

__device__ __align__(16) __nv_bfloat16 gxc [MPAD*K3];
__device__ __align__(16) __nv_bfloat16 gw1c[NQKV*K3];
__device__ __align__(16) __nv_bfloat16 gw2c[CDIM*K3];
__device__ __align__(16) __nv_bfloat16 gaoc[MPAD*K3];

__device__ __align__(16) __nv_bfloat16 g_qc [B_*H_*NTOK*192];  // [bh][n][hi|hi|lo]
__device__ __align__(16) __nv_bfloat16 g_kc [B_*H_*NTOK*192];  // [bh][n][hi|lo|hi]
__device__ __align__(16) __nv_bfloat16 g_vht[B_*H_*HD*NTOK];   // V^T hi: [bh][e][n]
__device__ __align__(16) __nv_bfloat16 g_vlt[B_*H_*HD*NTOK];   // V^T lo

// ---------------- split/concat kernels ----------------
__global__ __launch_bounds__(256) void split_x_kernel(const float* __restrict__ src)
{
    int i = blockIdx.x * 256 + threadIdx.x;
    if (i >= MPAD * CDIM) return;
    int row = i / CDIM, c = i - row * CDIM;
    float f = (row < MROWS) ? src[(size_t)row * CDIM + c] : 0.f;
    __nv_bfloat16 h = __float2bfloat16(f);
    __nv_bfloat16 l = __float2bfloat16(f - __bfloat162float(h));
    size_t base = (size_t)row * K3 + c;
    gxc[base]          = h;
    gxc[base + CDIM]   = h;
    gxc[base + 2*CDIM] = l;
}

__global__ __launch_bounds__(256) void split_w1_kernel(const float* __restrict__ src)
{
    int i = blockIdx.x * 256 + threadIdx.x;
    if (i >= NQKV * CDIM) return;
    int row = i / CDIM, c = i - row * CDIM;
    float f = src[(size_t)row * CDIM + c];
    __nv_bfloat16 h = __float2bfloat16(f);
    __nv_bfloat16 l = __float2bfloat16(f - __bfloat162float(h));
    size_t base = (size_t)row * K3 + c;
    gw1c[base]          = h;
    gw1c[base + CDIM]   = l;
    gw1c[base + 2*CDIM] = h;
}

__global__ __launch_bounds__(256) void split_w2_kernel(const float* __restrict__ src)
{
    int i = blockIdx.x * 256 + threadIdx.x;
    if (i >= CDIM * CDIM) return;
    int row = i / CDIM, c = i - row * CDIM;
    float f = src[(size_t)row * CDIM + c];
    __nv_bfloat16 h = __float2bfloat16(f);
    __nv_bfloat16 l = __float2bfloat16(f - __bfloat162float(h));
    size_t base = (size_t)row * K3 + c;
    gw2c[base]          = h;
    gw2c[base + CDIM]   = l;
    gw2c[base + 2*CDIM] = h;
}

// ---------------- warp mma + ldmatrix + cp.async ----------------
__device__ __forceinline__ void mma16816(float* d, const uint32_t* a, const uint32_t* b)
{
    asm volatile(
        "mma.sync.aligned.m16n8k16.row.col.f32.bf16.bf16.f32 "
        "{%0,%1,%2,%3}, {%4,%5,%6,%7}, {%8,%9}, {%0,%1,%2,%3};"
        : "+f"(d[0]), "+f"(d[1]), "+f"(d[2]), "+f"(d[3])
        : "r"(a[0]), "r"(a[1]), "r"(a[2]), "r"(a[3]), "r"(b[0]), "r"(b[1]));
}

__device__ __forceinline__ void ldsm4(uint32_t* r, uint32_t addr)
{
    asm volatile("ldmatrix.sync.aligned.m8n8.x4.shared.b16 {%0,%1,%2,%3}, [%4];"
        : "=r"(r[0]), "=r"(r[1]), "=r"(r[2]), "=r"(r[3]) : "r"(addr));
}

__device__ __forceinline__ void cpa16(uint32_t dst, const void* src)
{
    asm volatile("cp.async.cg.shared.global [%0], [%1], 16;" :: "r"(dst), "l"(src));
}
#define CP_COMMIT() asm volatile("cp.async.commit_group;" ::: "memory")
#define CP_WAIT(n)  asm volatile("cp.async.wait_group %0;" :: "n"(n) : "memory")

// D[128,128] = A[rows@m0][K3] @ B[rows@n0][K3]^T, fp32 accum.
// 256 threads, 8 warps 2(M)x4(N), warp tile 64x32. 3-stage cp.async pipeline,
// one __syncthreads per K-tile.
#define GSTG  10240                  // bytes per matrix per stage (128*40*2)
#define GEMM_SMEM (6 * GSTG)         // 61440

__device__ __forceinline__ void gemm_main(const __nv_bfloat16* __restrict__ A,
                                          const __nv_bfloat16* __restrict__ B,
                                          int m0, int n0, float acc[4][4][4],
                                          char* gsm)
{
    const int tid  = threadIdx.x;
    const int lane = tid & 31, wid = tid >> 5;
    const int wm = (wid & 1) * 64;
    const int wn = (wid >> 1) * 32;

    const int lr  = tid >> 1;         // 0..127
    const int lkb = (tid & 1) * 32;   // byte col offset: 0,32

    const uint32_t smA = (uint32_t)__cvta_generic_to_shared(gsm);
    const uint32_t smB = smA + 3 * GSTG;

    const char* Ap = (const char*)(A + (size_t)(m0 + lr) * K3) + lkb;
    const char* Bp = (const char*)(B + (size_t)(n0 + lr) * K3) + lkb;

    const uint32_t dA = smA + lr * 80 + lkb;
    const uint32_t dB = smB + lr * 80 + lkb;

    // ldmatrix lane-address bases (stage 0)
    const uint32_t aBase = smA + (wm + (lane & 15)) * 80 + (lane >> 4) * 16;
    const uint32_t bBase = smB + (wn + ((lane >> 4) * 8) + (lane & 7)) * 80
                               + ((lane >> 3) & 1) * 16;

    const int NKI = K3 / 32;          // 72

    // prologue: stages 0,1
    #pragma unroll
    for (int p = 0; p < 2; p++) {
        const size_t o = (size_t)p * 64;
        cpa16(dA + p * GSTG,      Ap + o);
        cpa16(dA + p * GSTG + 16, Ap + o + 16);
        cpa16(dB + p * GSTG,      Bp + o);
        cpa16(dB + p * GSTG + 16, Bp + o + 16);
        CP_COMMIT();
    }

    for (int t = 0; t < NKI; t++) {
        if (t + 1 < NKI) { CP_WAIT(1); } else { CP_WAIT(0); }
        __syncthreads();

        if (t + 2 < NKI) {
            const int s = (t + 2) % 3;
            const size_t o = (size_t)(t + 2) * 64;
            cpa16(dA + s * GSTG,      Ap + o);
            cpa16(dA + s * GSTG + 16, Ap + o + 16);
            cpa16(dB + s * GSTG,      Bp + o);
            cpa16(dB + s * GSTG + 16, Bp + o + 16);
            CP_COMMIT();
        }

        const uint32_t aB = aBase + (t % 3) * GSTG;
        const uint32_t bB = bBase + (t % 3) * GSTG;
        #pragma unroll
        for (int ks = 0; ks < 2; ks++) {
            uint32_t af[4][4], bfr[4][2];
            #pragma unroll
            for (int mt = 0; mt < 4; mt++)
                ldsm4(af[mt], aB + mt * (16 * 80) + ks * 32);
            #pragma unroll
            for (int np = 0; np < 2; np++) {
                uint32_t tmp[4];
                ldsm4(tmp, bB + np * (16 * 80) + ks * 32);
                bfr[2*np][0]   = tmp[0];
                bfr[2*np][1]   = tmp[1];
                bfr[2*np+1][0] = tmp[2];
                bfr[2*np+1][1] = tmp[3];
            }
            #pragma unroll
            for (int mt = 0; mt < 4; mt++)
                #pragma unroll
                for (int nt = 0; nt < 4; nt++)
                    mma16816(acc[mt][nt], af[mt], bfr[nt]);
        }
    }
}

// ---------------- QKV GEMM: epilogue writes attention-ready layouts ----------------
__global__ __launch_bounds__(256) void qkv_gemm_kernel()
{
    extern __shared__ char gsm[];
    const int n0 = blockIdx.x * 128;
    const int m0 = blockIdx.y * 128;

    float acc[4][4][4] = {};
    gemm_main(gxc, gw1c, m0, n0, acc, gsm);

    const int lane = threadIdx.x & 31, wid = threadIdx.x >> 5;
    const int wm = (wid & 1) * 64, wn = (wid >> 1) * 32;
    const int g = lane >> 2, tg = lane & 3;

    const int s3    = n0 / CDIM;
    const int nrem0 = n0 - s3 * CDIM;

    #pragma unroll
    for (int mt = 0; mt < 4; mt++) {
        #pragma unroll
        for (int nt = 0; nt < 4; nt++) {
            const int col = nrem0 + wn + nt * 8 + tg * 2;
            const int hh = col >> 6, e = col & 63;
            #pragma unroll
            for (int rr = 0; rr < 2; rr++) {
                const int mm = m0 + wm + mt * 16 + g + rr * 8;
                if (mm >= MROWS) continue;
                const int b = mm / NTOK;
                const int n = mm - b * NTOK;
                const size_t idx = (size_t)(b * H_ + hh) * NTOK + n;
                const float v0 = acc[mt][nt][rr * 2 + 0];
                const float v1 = acc[mt][nt][rr * 2 + 1];
                const __nv_bfloat16 h0 = __float2bfloat16(v0);
                const __nv_bfloat16 h1 = __float2bfloat16(v1);
                const __nv_bfloat16 l0 = __float2bfloat16(v0 - __bfloat162float(h0));
                const __nv_bfloat16 l1 = __float2bfloat16(v1 - __bfloat162float(h1));
                if (s3 == 0) {
                    __nv_bfloat16* qd = g_qc + idx * 192 + e;
                    qd[0]   = h0; qd[1]   = h1;
                    qd[64]  = h0; qd[65]  = h1;
                    qd[128] = l0; qd[129] = l1;
                    if (n < TTXT) { g_q[idx*HD + e] = v0; g_q[idx*HD + e + 1] = v1; }
                } else if (s3 == 1) {
                    __nv_bfloat16* kd = g_kc + idx * 192 + e;
                    kd[0]   = h0; kd[1]   = h1;
                    kd[64]  = l0; kd[65]  = l1;
                    kd[128] = h0; kd[129] = h1;
                    if (n < TTXT) { g_k[idx*HD + e] = v0; g_k[idx*HD + e + 1] = v1; }
                } else {
                    const size_t vi = ((size_t)(b * H_ + hh) * HD + e) * NTOK + n;
                    g_vht[vi]        = h0;
                    g_vht[vi + NTOK] = h1;
                    g_vlt[vi]        = l0;
                    g_vlt[vi + NTOK] = l1;
                    if (n < TTXT) { g_v[idx*HD + e] = v0; g_v[idx*HD + e + 1] = v1; }
                }
            }
        }
    }
}

// ---------------- proj GEMM kernel ----------------
__global__ __launch_bounds__(256) void proj_gemm_kernel(const float* __restrict__ bias,
                                                        float* __restrict__ out)
{
    extern __shared__ char gsm[];
    const int n0 = blockIdx.x * 128;
    const int m0 = blockIdx.y * 128;

    float acc[4][4][4] = {};
    gemm_main(gaoc, gw2c, m0, n0, acc, gsm);

    const int lane = threadIdx.x & 31, wid = threadIdx.x >> 5;
    const int wm = (wid & 1) * 64, wn = (wid >> 1) * 32;
    const int g = lane >> 2, tg = lane & 3;

    #pragma unroll
    for (int mt = 0; mt < 4; mt++) {
        #pragma unroll
        for (int nt = 0; nt < 4; nt++) {
            const int d = n0 + wn + nt * 8 + tg * 2;
            const float b0 = bias[d], b1 = bias[d + 1];
            #pragma unroll
            for (int rr = 0; rr < 2; rr++) {
                const int m = m0 + wm + mt * 16 + g + rr * 8;
                if (m >= MROWS) continue;
                out[(size_t)m * CDIM + d]     = acc[mt][nt][rr * 2 + 0] + b0;
                out[(size_t)m * CDIM + d + 1] = acc[mt][nt][rr * 2 + 1] + b1;
            }
        }
    }
}

// ---------------- gaoc split-store (A-side hi|hi|lo) ----------------
__device__ __forceinline__ void store_split3(int row, int c, float v)
{
    __nv_bfloat16 h = __float2bfloat16(v);
    __nv_bfloat16 l = __float2bfloat16(v - __bfloat162float(h));
    size_t base = (size_t)row * K3 + c;
    gaoc[base]          = h;
    gaoc[base + CDIM]   = h;
    gaoc[base + 2*CDIM] = l;
}

// ---------------- text attention (fp32, tiny) ----------------
__global__ __launch_bounds__(64) void text_attn_kernel()
{
    const int bh = blockIdx.x;
    const int b = bh / H_;
    const int h = bh - b * H_;

    __shared__ float Kt[TTXT][HD];
    __shared__ float Vt[TTXT][HD];

    const size_t base = (size_t)(b*H_ + h) * NTOK * HD;
    const float* kbase = g_k + base;
    const float* vbase = g_v + base;

    const int tid = threadIdx.x;
    for (int i = tid; i < TTXT*HD; i += 64) {
        Kt[i / HD][i % HD] = kbase[i];
        Vt[i / HD][i % HD] = vbase[i];
    }
    __syncthreads();

    if (tid < TTXT) {
        const float* qrow = g_q + base + (size_t)tid * HD;
        float qv[HD];
        #pragma unroll
        for (int e = 0; e < HD; e++) qv[e] = qrow[e];

        float sc[TTXT];
        float mx = -1e30f;
        #pragma unroll 4
        for (int s = 0; s < TTXT; s++) {
            float d = 0.f;
            #pragma unroll
            for (int e = 0; e < HD; e++) d += qv[e] * Kt[s][e];
            d *= 0.125f;
            sc[s] = d;
            mx = fmaxf(mx, d);
        }
        float sum = 0.f;
        #pragma unroll
        for (int s = 0; s < TTXT; s++) { sc[s] = __expf(sc[s] - mx); sum += sc[s]; }
        float inv = 1.f / sum;

        const int row = b * NTOK + tid;
        #pragma unroll 4
        for (int e = 0; e < HD; e++) {
            float a = 0.f;
            #pragma unroll
            for (int s = 0; s < TTXT; s++) a += sc[s] * Vt[s][e];
            store_split3(row, h * HD + e, a * inv);
        }
    }
}

// ---------------- image attention: mma flash kernel (128-query blocks) ----------------
#define QPITCH 200
#define VPITCH 72
#define OFF_K  51200
#define OFF_VH 76800
#define OFF_VL 86016
#define IMG_SMEM2 95232

__device__ __forceinline__ void pack_hilo(float x, float y, uint32_t& hi, uint32_t& lo)
{
    __nv_bfloat162 h = __floats2bfloat162_rn(x, y);
    float hx = __bfloat162float(h.x), hy = __bfloat162float(h.y);
    __nv_bfloat162 l = __floats2bfloat162_rn(x - hx, y - hy);
    hi = *(uint32_t*)&h;
    lo = *(uint32_t*)&l;
}

__global__ __launch_bounds__(128) void img_attn_mma_kernel()
{
    extern __shared__ char smx[];
    __nv_bfloat16* Qs = (__nv_bfloat16*)(smx);            // [128][200]
    __nv_bfloat16* Ks = (__nv_bfloat16*)(smx + OFF_K);    // [64][200]
    __nv_bfloat16* Vh = (__nv_bfloat16*)(smx + OFF_VH);   // [64][72]
    __nv_bfloat16* Vl = (__nv_bfloat16*)(smx + OFF_VL);   // [64][72]

    const int bh = blockIdx.y;
    const int q0 = blockIdx.x * 128;
    const int tid = threadIdx.x;
    const int lane = tid & 31, wid = tid >> 5;
    const int g = lane >> 2, tg = lane & 3;
    const int wrow = wid * 32;            // 32 query rows per warp (mt=2)

    const uint32_t ksAddr = (uint32_t)__cvta_generic_to_shared(Ks);
    const uint32_t vhAddr = (uint32_t)__cvta_generic_to_shared(Vh);
    const uint32_t vlAddr = (uint32_t)__cvta_generic_to_shared(Vl);

    const uint32_t qBase = (uint32_t)__cvta_generic_to_shared(
        Qs + (wrow + (lane & 15)) * QPITCH + (lane >> 4) * 8);
    const uint32_t kBase = ksAddr
        + ((((lane >> 4) * 8) + (lane & 7)) * QPITCH + ((lane >> 3) & 1) * 8) * 2;
    const uint32_t vhBase = vhAddr
        + ((((lane >> 4) * 8) + (lane & 7)) * VPITCH + ((lane >> 3) & 1) * 8) * 2;
    const uint32_t vlBase = vlAddr
        + ((((lane >> 4) * 8) + (lane & 7)) * VPITCH + ((lane >> 3) & 1) * 8) * 2;

    // load Q tile (128 rows x 192)
    {
        const __nv_bfloat16* qsrc = g_qc + ((size_t)bh * NTOK + TTXT + q0) * 192;
        for (int u = tid; u < 128 * 24; u += 128) {
            int r = u / 24, o = (u % 24) * 8;
            *(uint4*)&Qs[r * QPITCH + o] = *(const uint4*)(qsrc + (size_t)r * 192 + o);
        }
    }

    float mrow[2][2], lrow[2][2];
    #pragma unroll
    for (int mt = 0; mt < 2; mt++) { mrow[mt][0] = mrow[mt][1] = -1e30f; lrow[mt][0] = lrow[mt][1] = 0.f; }

    float O[2][8][4];
    #pragma unroll
    for (int mt = 0; mt < 2; mt++)
        #pragma unroll
        for (int nt = 0; nt < 8; nt++)
            #pragma unroll
            for (int j = 0; j < 4; j++) O[mt][nt][j] = 0.f;

    const __nv_bfloat16* kcb = g_kc + (size_t)bh * NTOK * 192;
    const __nv_bfloat16* vhb = g_vht + (size_t)bh * HD * NTOK;
    const __nv_bfloat16* vlb = g_vlt + (size_t)bh * HD * NTOK;

    for (int t = 0; t < 17; t++) {
        const int j0 = t * 64;
        __syncthreads();

        for (int u = tid; u < 64 * 24; u += 128) {
            int r = u / 24, o = (u % 24) * 8;
            if (j0 + r < NTOK)
                cpa16(ksAddr + (r * QPITCH + o) * 2, kcb + (size_t)(j0 + r) * 192 + o);
            else
                *(uint4*)&Ks[r * QPITCH + o] = make_uint4(0u, 0u, 0u, 0u);
        }
        for (int u = tid; u < 64 * 8; u += 128) {
            int e = u >> 3, o = (u & 7) * 8;
            if (j0 + o + 7 < NTOK) {
                cpa16(vhAddr + (e * VPITCH + o) * 2, vhb + (size_t)e * NTOK + j0 + o);
                cpa16(vlAddr + (e * VPITCH + o) * 2, vlb + (size_t)e * NTOK + j0 + o);
            } else {
                *(uint4*)&Vh[e * VPITCH + o] = make_uint4(0u, 0u, 0u, 0u);
                *(uint4*)&Vl[e * VPITCH + o] = make_uint4(0u, 0u, 0u, 0u);
            }
        }
        CP_COMMIT();
        CP_WAIT(0);
        __syncthreads();

        float S[2][8][4];
        #pragma unroll
        for (int mt = 0; mt < 2; mt++)
            #pragma unroll
            for (int nt = 0; nt < 8; nt++)
                #pragma unroll
                for (int j = 0; j < 4; j++) S[mt][nt][j] = 0.f;

        #pragma unroll
        for (int ks = 0; ks < 12; ks++) {
            uint32_t a[2][4];
            ldsm4(a[0], qBase + ks * 32);
            ldsm4(a[1], qBase + 16 * (QPITCH * 2) + ks * 32);
            uint32_t bfr[8][2];
            #pragma unroll
            for (int np = 0; np < 4; np++) {
                uint32_t tmp[4];
                ldsm4(tmp, kBase + np * (16 * QPITCH * 2) + ks * 32);
                bfr[2*np][0]   = tmp[0];
                bfr[2*np][1]   = tmp[1];
                bfr[2*np+1][0] = tmp[2];
                bfr[2*np+1][1] = tmp[3];
            }
            #pragma unroll
            for (int nt = 0; nt < 8; nt++) {
                mma16816(S[0][nt], a[0], bfr[nt]);
                mma16816(S[1][nt], a[1], bfr[nt]);
            }
        }

        #pragma unroll
        for (int mt = 0; mt < 2; mt++) {
            #pragma unroll
            for (int nt = 0; nt < 8; nt++) {
                const int key = j0 + nt * 8 + tg * 2;
                const bool v0 = key < NTOK, v1 = key + 1 < NTOK;
                S[mt][nt][0] = v0 ? S[mt][nt][0] * 0.125f : -1e30f;
                S[mt][nt][1] = v1 ? S[mt][nt][1] * 0.125f : -1e30f;
                S[mt][nt][2] = v0 ? S[mt][nt][2] * 0.125f : -1e30f;
                S[mt][nt][3] = v1 ? S[mt][nt][3] * 0.125f : -1e30f;
            }

            float t0 = -1e30f, t1 = -1e30f;
            #pragma unroll
            for (int nt = 0; nt < 8; nt++) {
                t0 = fmaxf(t0, fmaxf(S[mt][nt][0], S[mt][nt][1]));
                t1 = fmaxf(t1, fmaxf(S[mt][nt][2], S[mt][nt][3]));
            }
            t0 = fmaxf(t0, __shfl_xor_sync(0xffffffffu, t0, 1));
            t0 = fmaxf(t0, __shfl_xor_sync(0xffffffffu, t0, 2));
            t1 = fmaxf(t1, __shfl_xor_sync(0xffffffffu, t1, 1));
            t1 = fmaxf(t1, __shfl_xor_sync(0xffffffffu, t1, 2));

            const float mn0 = fmaxf(mrow[mt][0], t0), mn1 = fmaxf(mrow[mt][1], t1);
            const float al0 = __expf(mrow[mt][0] - mn0), al1 = __expf(mrow[mt][1] - mn1);
            mrow[mt][0] = mn0; mrow[mt][1] = mn1;

            float rs0 = 0.f, rs1 = 0.f;
            #pragma unroll
            for (int nt = 0; nt < 8; nt++) {
                S[mt][nt][0] = __expf(S[mt][nt][0] - mn0);
                S[mt][nt][1] = __expf(S[mt][nt][1] - mn0);
                S[mt][nt][2] = __expf(S[mt][nt][2] - mn1);
                S[mt][nt][3] = __expf(S[mt][nt][3] - mn1);
                rs0 += S[mt][nt][0] + S[mt][nt][1];
                rs1 += S[mt][nt][2] + S[mt][nt][3];
            }
            rs0 += __shfl_xor_sync(0xffffffffu, rs0, 1);
            rs0 += __shfl_xor_sync(0xffffffffu, rs0, 2);
            rs1 += __shfl_xor_sync(0xffffffffu, rs1, 1);
            rs1 += __shfl_xor_sync(0xffffffffu, rs1, 2);
            lrow[mt][0] = lrow[mt][0] * al0 + rs0;
            lrow[mt][1] = lrow[mt][1] * al1 + rs1;

            #pragma unroll
            for (int nt = 0; nt < 8; nt++) {
                O[mt][nt][0] *= al0; O[mt][nt][1] *= al0;
                O[mt][nt][2] *= al1; O[mt][nt][3] *= al1;
            }
        }

        uint32_t ph[2][4][4], pl[2][4][4];
        #pragma unroll
        for (int mt = 0; mt < 2; mt++) {
            #pragma unroll
            for (int ks = 0; ks < 4; ks++) {
                pack_hilo(S[mt][2*ks][0],   S[mt][2*ks][1],   ph[mt][ks][0], pl[mt][ks][0]);
                pack_hilo(S[mt][2*ks][2],   S[mt][2*ks][3],   ph[mt][ks][1], pl[mt][ks][1]);
                pack_hilo(S[mt][2*ks+1][0], S[mt][2*ks+1][1], ph[mt][ks][2], pl[mt][ks][2]);
                pack_hilo(S[mt][2*ks+1][2], S[mt][2*ks+1][3], ph[mt][ks][3], pl[mt][ks][3]);
            }
        }

        #pragma unroll
        for (int ks = 0; ks < 4; ks++) {
            uint32_t vh2[8][2], vl2[8][2];
            #pragma unroll
            for (int np = 0; np < 4; np++) {
                uint32_t th[4], tl[4];
                ldsm4(th, vhBase + np * (16 * VPITCH * 2) + ks * 32);
                ldsm4(tl, vlBase + np * (16 * VPITCH * 2) + ks * 32);
                vh2[2*np][0] = th[0]; vh2[2*np][1] = th[1];
                vh2[2*np+1][0] = th[2]; vh2[2*np+1][1] = th[3];
                vl2[2*np][0] = tl[0]; vl2[2*np][1] = tl[1];
                vl2[2*np+1][0] = tl[2]; vl2[2*np+1][1] = tl[3];
            }
            #pragma unroll
            for (int nt = 0; nt < 8; nt++) {
                #pragma unroll
                for (int mt = 0; mt < 2; mt++) {
                    mma16816(O[mt][nt], ph[mt][ks], vh2[nt]);
                    mma16816(O[mt][nt], ph[mt][ks], vl2[nt]);
                    mma16816(O[mt][nt], pl[mt][ks], vh2[nt]);
                }
            }
        }
    }

    // epilogue
    const int b = bh / H_, h = bh - b * H_;
    #pragma unroll
    for (int mt = 0; mt < 2; mt++) {
        const float inv0 = 1.f / lrow[mt][0], inv1 = 1.f / lrow[mt][1];
        const int row0 = b * NTOK + TTXT + q0 + wrow + mt * 16 + g;
        const int row1 = row0 + 8;
        #pragma unroll
        for (int nt = 0; nt < 8; nt++) {
            const int c = h * HD + nt * 8 + tg * 2;
            store_split3(row0, c,     O[mt][nt][0] * inv0);
            store_split3(row0, c + 1, O[mt][nt][1] * inv0);
            store_split3(row1, c,     O[mt][nt][2] * inv1);
            store_split3(row1, c + 1, O[mt][nt][3] * inv1);
        }
    }
}

// ---------------- launch ----------------
extern "C" void kernel_launch(void* const* d_in, const int* in_sizes, int n_in,
                              void* d_out, int out_size)
{
    const float* x      = (const float*)d_in[0];
    const float* qkv_w  = (const float*)d_in[1];
    const float* proj_w = (const float*)d_in[2];
    const float* proj_b = (const float*)d_in[3];
    float* out = (float*)d_out;

    cudaFuncSetAttribute(img_attn_mma_kernel,
                         cudaFuncAttributeMaxDynamicSharedMemorySize, IMG_SMEM2);
    cudaFuncSetAttribute(qkv_gemm_kernel,
                         cudaFuncAttributeMaxDynamicSharedMemorySize, GEMM_SMEM);
    cudaFuncSetAttribute(proj_gemm_kernel,
                         cudaFuncAttributeMaxDynamicSharedMemorySize, GEMM_SMEM);

    split_x_kernel <<<(MPAD*CDIM + 255)/256, 256>>>(x);
    split_w1_kernel<<<(NQKV*CDIM + 255)/256, 256>>>(qkv_w);
    split_w2_kernel<<<(CDIM*CDIM + 255)/256, 256>>>(proj_w);

    qkv_gemm_kernel<<<dim3(NQKV/128, MPAD/128), 256, GEMM_SMEM>>>();

    text_attn_kernel<<<B_*H_, 64>>>();
    img_attn_mma_kernel<<<dim3(SIMG/128, B_*H_), 128, IMG_SMEM2>>>();

    proj_gemm_kernel<<<dim3(CDIM/128, MPAD/128), 256, GEMM_SMEM>>>(proj_b, out);
}

// round 12
// speedup vs baseline: 1.2105x; 1.2105x over previous
#include <cuda_runtime.h>
#include <cuda_bf16.h>
#include <cstdint>

// ---------------- problem constants ----------------
#define B_    8
#define TTXT  40
#define SIMG  1024
#define NTOK  1064
#define CDIM  768
#define H_    12
#define HD    64
#define MROWS (B_*NTOK)       // 8512
#define MPAD  8576            // 67*128
#define K3    (3*CDIM)        // 2304
#define NQKV  (3*CDIM)        // 2304

// ---------------- device scratch (referenced ONLY from device code) ----------------
__device__ float g_q [B_*H_*NTOK*HD];
__device__ float g_k [B_*H_*NTOK*HD];
__device__ float g_v [B_*H_*NTOK*HD];

__device__ __align__(16) __nv_bfloat16 gxc [MPAD*K3];
__device__ __align__(16) __nv_bfloat16 gw1c[NQKV*K3];
__device__ __align__(16) __nv_bfloat16 gw2c[CDIM*K3];
__device__ __align__(16) __nv_bfloat16 gaoc[MPAD*K3];

__device__ __align__(16) __nv_bfloat16 g_qc [B_*H_*NTOK*192];  // [bh][n][hi|hi|lo]
__device__ __align__(16) __nv_bfloat16 g_kc [B_*H_*NTOK*192];  // [bh][n][hi|lo|hi]
__device__ __align__(16) __nv_bfloat16 g_vht[B_*H_*HD*NTOK];   // V^T hi: [bh][e][n]
__device__ __align__(16) __nv_bfloat16 g_vlt[B_*H_*HD*NTOK];   // V^T lo

// ---------------- split/concat kernels ----------------
__global__ __launch_bounds__(256) void split_x_kernel(const float* __restrict__ src)
{
    int i = blockIdx.x * 256 + threadIdx.x;
    if (i >= MPAD * CDIM) return;
    int row = i / CDIM, c = i - row * CDIM;
    float f = (row < MROWS) ? src[(size_t)row * CDIM + c] : 0.f;
    __nv_bfloat16 h = __float2bfloat16(f);
    __nv_bfloat16 l = __float2bfloat16(f - __bfloat162float(h));
    size_t base = (size_t)row * K3 + c;
    gxc[base]          = h;
    gxc[base + CDIM]   = h;
    gxc[base + 2*CDIM] = l;
}

__global__ __launch_bounds__(256) void split_w1_kernel(const float* __restrict__ src)
{
    int i = blockIdx.x * 256 + threadIdx.x;
    if (i >= NQKV * CDIM) return;
    int row = i / CDIM, c = i - row * CDIM;
    float f = src[(size_t)row * CDIM + c];
    __nv_bfloat16 h = __float2bfloat16(f);
    __nv_bfloat16 l = __float2bfloat16(f - __bfloat162float(h));
    size_t base = (size_t)row * K3 + c;
    gw1c[base]          = h;
    gw1c[base + CDIM]   = l;
    gw1c[base + 2*CDIM] = h;
}

__global__ __launch_bounds__(256) void split_w2_kernel(const float* __restrict__ src)
{
    int i = blockIdx.x * 256 + threadIdx.x;
    if (i >= CDIM * CDIM) return;
    int row = i / CDIM, c = i - row * CDIM;
    float f = src[(size_t)row * CDIM + c];
    __nv_bfloat16 h = __float2bfloat16(f);
    __nv_bfloat16 l = __float2bfloat16(f - __bfloat162float(h));
    size_t base = (size_t)row * K3 + c;
    gw2c[base]          = h;
    gw2c[base + CDIM]   = l;
    gw2c[base + 2*CDIM] = h;
}

// ---------------- warp mma + ldmatrix + cp.async ----------------
__device__ __forceinline__ void mma16816(float* d, const uint32_t* a, const uint32_t* b)
{
    asm volatile(
        "mma.sync.aligned.m16n8k16.row.col.f32.bf16.bf16.f32 "
        "{%0,%1,%2,%3}, {%4,%5,%6,%7}, {%8,%9}, {%0,%1,%2,%3};"
        : "+f"(d[0]), "+f"(d[1]), "+f"(d[2]), "+f"(d[3])
        : "r"(a[0]), "r"(a[1]), "r"(a[2]), "r"(a[3]), "r"(b[0]), "r"(b[1]));
}

__device__ __forceinline__ void ldsm4(uint32_t* r, uint32_t addr)
{
    asm volatile("ldmatrix.sync.aligned.m8n8.x4.shared.b16 {%0,%1,%2,%3}, [%4];"
        : "=r"(r[0]), "=r"(r[1]), "=r"(r[2]), "=r"(r[3]) : "r"(addr));
}

__device__ __forceinline__ void cpa16(uint32_t dst, const void* src)
{
    asm volatile("cp.async.cg.shared.global [%0], [%1], 16;" :: "r"(dst), "l"(src));
}
#define CP_COMMIT() asm volatile("cp.async.commit_group;" ::: "memory")
#define CP_WAIT(n)  asm volatile("cp.async.wait_group %0;" :: "n"(n) : "memory")

// D[128,128] = A[rows@m0][K3] @ B[rows@n0][K3]^T, fp32 accum.  (round-10 verbatim)
// 128 threads, 4 warps 2x2, warp tile 64x64. 3-stage cp.async pipeline,
// ONE __syncthreads per K-tile (prefetch issued after the barrier).
#define GSTG  10240                  // bytes per matrix per stage (128*40*2)
#define GEMM_SMEM (6 * GSTG)         // 61440

__device__ __forceinline__ void gemm_main(const __nv_bfloat16* __restrict__ A,
                                          const __nv_bfloat16* __restrict__ B,
                                          int m0, int n0, float acc[4][8][4],
                                          char* gsm)
{
    const int tid  = threadIdx.x;
    const int lane = tid & 31, wid = tid >> 5;
    const int wm = (wid & 1) * 64;
    const int wn = (wid >> 1) * 64;

    const int lr = tid >> 2;          // 0..31
    const int lkb = (tid & 3) * 16;   // byte col offset: 0,16,32,48

    const uint32_t smA = (uint32_t)__cvta_generic_to_shared(gsm);
    const uint32_t smB = smA + 3 * GSTG;

    const char* Ap = (const char*)(A + (size_t)(m0 + lr) * K3) + lkb;
    const char* Bp = (const char*)(B + (size_t)(n0 + lr) * K3) + lkb;

    const uint32_t dA = smA + lr * 80 + lkb;
    const uint32_t dB = smB + lr * 80 + lkb;

    const uint32_t aBase = smA + (wm + (lane & 15)) * 80 + (lane >> 4) * 16;
    const uint32_t bBase = smB + (wn + ((lane >> 4) * 8) + (lane & 7)) * 80
                               + ((lane >> 3) & 1) * 16;

    const int NKI = K3 / 32;          // 72

    #pragma unroll
    for (int p = 0; p < 2; p++) {
        const size_t o = (size_t)p * 64;
        #pragma unroll
        for (int i = 0; i < 4; i++) {
            cpa16(dA + p * GSTG + (32*i) * 80, Ap + o + (size_t)(32*i) * K3 * 2);
            cpa16(dB + p * GSTG + (32*i) * 80, Bp + o + (size_t)(32*i) * K3 * 2);
        }
        CP_COMMIT();
    }

    for (int t = 0; t < NKI; t++) {
        if (t + 1 < NKI) { CP_WAIT(1); } else { CP_WAIT(0); }
        __syncthreads();

        if (t + 2 < NKI) {
            const int s = (t + 2) % 3;
            const size_t o = (size_t)(t + 2) * 64;
            #pragma unroll
            for (int i = 0; i < 4; i++) {
                cpa16(dA + s * GSTG + (32*i) * 80, Ap + o + (size_t)(32*i) * K3 * 2);
                cpa16(dB + s * GSTG + (32*i) * 80, Bp + o + (size_t)(32*i) * K3 * 2);
            }
            CP_COMMIT();
        }

        const uint32_t aB = aBase + (t % 3) * GSTG;
        const uint32_t bB = bBase + (t % 3) * GSTG;
        #pragma unroll
        for (int ks = 0; ks < 2; ks++) {
            uint32_t af[4][4], bfr[8][2];
            #pragma unroll
            for (int mt = 0; mt < 4; mt++)
                ldsm4(af[mt], aB + mt * (16 * 80) + ks * 32);
            #pragma unroll
            for (int np = 0; np < 4; np++) {
                uint32_t tmp[4];
                ldsm4(tmp, bB + np * (16 * 80) + ks * 32);
                bfr[2*np][0]   = tmp[0];
                bfr[2*np][1]   = tmp[1];
                bfr[2*np+1][0] = tmp[2];
                bfr[2*np+1][1] = tmp[3];
            }
            #pragma unroll
            for (int mt = 0; mt < 4; mt++)
                #pragma unroll
                for (int nt = 0; nt < 8; nt++)
                    mma16816(acc[mt][nt], af[mt], bfr[nt]);
        }
    }
}

// ---------------- QKV GEMM: epilogue writes attention-ready layouts ----------------
__global__ __launch_bounds__(128) void qkv_gemm_kernel()
{
    extern __shared__ char gsm[];
    const int n0 = blockIdx.x * 128;
    const int m0 = blockIdx.y * 128;

    float acc[4][8][4] = {};
    gemm_main(gxc, gw1c, m0, n0, acc, gsm);

    const int lane = threadIdx.x & 31, wid = threadIdx.x >> 5;
    const int wm = (wid & 1) * 64, wn = (wid >> 1) * 64;
    const int g = lane >> 2, tg = lane & 3;

    const int s3    = n0 / CDIM;
    const int nrem0 = n0 - s3 * CDIM;

    #pragma unroll
    for (int mt = 0; mt < 4; mt++) {
        #pragma unroll
        for (int nt = 0; nt < 8; nt++) {
            const int col = nrem0 + wn + nt * 8 + tg * 2;
            const int hh = col >> 6, e = col & 63;
            #pragma unroll
            for (int rr = 0; rr < 2; rr++) {
                const int mm = m0 + wm + mt * 16 + g + rr * 8;
                if (mm >= MROWS) continue;
                const int b = mm / NTOK;
                const int n = mm - b * NTOK;
                const size_t idx = (size_t)(b * H_ + hh) * NTOK + n;
                const float v0 = acc[mt][nt][rr * 2 + 0];
                const float v1 = acc[mt][nt][rr * 2 + 1];
                const __nv_bfloat16 h0 = __float2bfloat16(v0);
                const __nv_bfloat16 h1 = __float2bfloat16(v1);
                const __nv_bfloat16 l0 = __float2bfloat16(v0 - __bfloat162float(h0));
                const __nv_bfloat16 l1 = __float2bfloat16(v1 - __bfloat162float(h1));
                if (s3 == 0) {
                    __nv_bfloat16* qd = g_qc + idx * 192 + e;
                    qd[0]   = h0; qd[1]   = h1;
                    qd[64]  = h0; qd[65]  = h1;
                    qd[128] = l0; qd[129] = l1;
                    if (n < TTXT) { g_q[idx*HD + e] = v0; g_q[idx*HD + e + 1] = v1; }
                } else if (s3 == 1) {
                    __nv_bfloat16* kd = g_kc + idx * 192 + e;
                    kd[0]   = h0; kd[1]   = h1;
                    kd[64]  = l0; kd[65]  = l1;
                    kd[128] = h0; kd[129] = h1;
                    if (n < TTXT) { g_k[idx*HD + e] = v0; g_k[idx*HD + e + 1] = v1; }
                } else {
                    const size_t vi = ((size_t)(b * H_ + hh) * HD + e) * NTOK + n;
                    g_vht[vi]        = h0;
                    g_vht[vi + NTOK] = h1;
                    g_vlt[vi]        = l0;
                    g_vlt[vi + NTOK] = l1;
                    if (n < TTXT) { g_v[idx*HD + e] = v0; g_v[idx*HD + e + 1] = v1; }
                }
            }
        }
    }
}

// ---------------- proj GEMM kernel ----------------
__global__ __launch_bounds__(128) void proj_gemm_kernel(const float* __restrict__ bias,
                                                        float* __restrict__ out)
{
    extern __shared__ char gsm[];
    const int n0 = blockIdx.x * 128;
    const int m0 = blockIdx.y * 128;

    float acc[4][8][4] = {};
    gemm_main(gaoc, gw2c, m0, n0, acc, gsm);

    const int lane = threadIdx.x & 31, wid = threadIdx.x >> 5;
    const int wm = (wid & 1) * 64, wn = (wid >> 1) * 64;
    const int g = lane >> 2, tg = lane & 3;

    #pragma unroll
    for (int mt = 0; mt < 4; mt++) {
        #pragma unroll
        for (int nt = 0; nt < 8; nt++) {
            const int d = n0 + wn + nt * 8 + tg * 2;
            const float b0 = bias[d], b1 = bias[d + 1];
            #pragma unroll
            for (int rr = 0; rr < 2; rr++) {
                const int m = m0 + wm + mt * 16 + g + rr * 8;
                if (m >= MROWS) continue;
                out[(size_t)m * CDIM + d]     = acc[mt][nt][rr * 2 + 0] + b0;
                out[(size_t)m * CDIM + d + 1] = acc[mt][nt][rr * 2 + 1] + b1;
            }
        }
    }
}

// ---------------- gaoc split-store (A-side hi|hi|lo) ----------------
__device__ __forceinline__ void store_split3(int row, int c, float v)
{
    __nv_bfloat16 h = __float2bfloat16(v);
    __nv_bfloat16 l = __float2bfloat16(v - __bfloat162float(h));
    size_t base = (size_t)row * K3 + c;
    gaoc[base]          = h;
    gaoc[base + CDIM]   = h;
    gaoc[base + 2*CDIM] = l;
}

// ---------------- text attention (fp32, tiny) ----------------
__global__ __launch_bounds__(64) void text_attn_kernel()
{
    const int bh = blockIdx.x;
    const int b = bh / H_;
    const int h = bh - b * H_;

    __shared__ float Kt[TTXT][HD];
    __shared__ float Vt[TTXT][HD];

    const size_t base = (size_t)(b*H_ + h) * NTOK * HD;
    const float* kbase = g_k + base;
    const float* vbase = g_v + base;

    const int tid = threadIdx.x;
    for (int i = tid; i < TTXT*HD; i += 64) {
        Kt[i / HD][i % HD] = kbase[i];
        Vt[i / HD][i % HD] = vbase[i];
    }
    __syncthreads();

    if (tid < TTXT) {
        const float* qrow = g_q + base + (size_t)tid * HD;
        float qv[HD];
        #pragma unroll
        for (int e = 0; e < HD; e++) qv[e] = qrow[e];

        float sc[TTXT];
        float mx = -1e30f;
        #pragma unroll 4
        for (int s = 0; s < TTXT; s++) {
            float d = 0.f;
            #pragma unroll
            for (int e = 0; e < HD; e++) d += qv[e] * Kt[s][e];
            d *= 0.125f;
            sc[s] = d;
            mx = fmaxf(mx, d);
        }
        float sum = 0.f;
        #pragma unroll
        for (int s = 0; s < TTXT; s++) { sc[s] = __expf(sc[s] - mx); sum += sc[s]; }
        float inv = 1.f / sum;

        const int row = b * NTOK + tid;
        #pragma unroll 4
        for (int e = 0; e < HD; e++) {
            float a = 0.f;
            #pragma unroll
            for (int s = 0; s < TTXT; s++) a += sc[s] * Vt[s][e];
            store_split3(row, h * HD + e, a * inv);
        }
    }
}

// ---------------- image attention: mma flash kernel (128-query blocks) ----------------
// smem: Q[128][200] | K[64][200] | Vh[2][64][72] | Vl[2][64][72]
#define QPITCH 200
#define VPITCH 72
#define OFF_K  51200
#define OFF_VH 76800
#define VSTG   9216
#define OFF_VL (OFF_VH + 2*VSTG)     // 95232
#define IMG_SMEM2 (OFF_VL + 2*VSTG)  // 113664

__device__ __forceinline__ void pack_hilo(float x, float y, uint32_t& hi, uint32_t& lo)
{
    __nv_bfloat162 h = __floats2bfloat162_rn(x, y);
    float hx = __bfloat162float(h.x), hy = __bfloat162float(h.y);
    __nv_bfloat162 l = __floats2bfloat162_rn(x - hx, y - hy);
    hi = *(uint32_t*)&h;
    lo = *(uint32_t*)&l;
}

__global__ __launch_bounds__(128) void img_attn_mma_kernel()
{
    extern __shared__ char smx[];
    __nv_bfloat16* Qs = (__nv_bfloat16*)(smx);            // [128][200]
    __nv_bfloat16* Ks = (__nv_bfloat16*)(smx + OFF_K);    // [64][200]

    const int bh = blockIdx.y;
    const int q0 = blockIdx.x * 128;
    const int tid = threadIdx.x;
    const int lane = tid & 31, wid = tid >> 5;
    const int g = lane >> 2, tg = lane & 3;
    const int wrow = wid * 32;            // 32 query rows per warp (mt=2)

    const uint32_t ksAddr = (uint32_t)__cvta_generic_to_shared(Ks);
    const uint32_t vhAddr = (uint32_t)__cvta_generic_to_shared(smx + OFF_VH);
    const uint32_t vlAddr = (uint32_t)__cvta_generic_to_shared(smx + OFF_VL);

    const uint32_t qBase = (uint32_t)__cvta_generic_to_shared(
        Qs + (wrow + (lane & 15)) * QPITCH + (lane >> 4) * 8);
    const uint32_t kBase = ksAddr
        + ((((lane >> 4) * 8) + (lane & 7)) * QPITCH + ((lane >> 3) & 1) * 8) * 2;
    const uint32_t vfragOff =
        ((((lane >> 4) * 8) + (lane & 7)) * VPITCH + ((lane >> 3) & 1) * 8) * 2;

    const __nv_bfloat16* kcb = g_kc + (size_t)bh * NTOK * 192;
    const __nv_bfloat16* vhb = g_vht + (size_t)bh * HD * NTOK;
    const __nv_bfloat16* vlb = g_vlt + (size_t)bh * HD * NTOK;

    // K-tile loader (zero-fill out-of-range with plain stores)
    auto load_k = [&](int jj) {
        for (int u = tid; u < 64 * 24; u += 128) {
            int r = u / 24, o = (u % 24) * 8;
            if (jj + r < NTOK)
                cpa16(ksAddr + (r * QPITCH + o) * 2, kcb + (size_t)(jj + r) * 192 + o);
            else
                *(uint4*)&Ks[r * QPITCH + o] = make_uint4(0u, 0u, 0u, 0u);
        }
    };
    auto load_v = [&](int jj, int stg) {
        const uint32_t vhD = vhAddr + stg * VSTG;
        const uint32_t vlD = vlAddr + stg * VSTG;
        __nv_bfloat16* VhP = (__nv_bfloat16*)(smx + OFF_VH + stg * VSTG);
        __nv_bfloat16* VlP = (__nv_bfloat16*)(smx + OFF_VL + stg * VSTG);
        for (int u = tid; u < 64 * 8; u += 128) {
            int e = u >> 3, o = (u & 7) * 8;
            if (jj + o + 7 < NTOK) {
                cpa16(vhD + (e * VPITCH + o) * 2, vhb + (size_t)e * NTOK + jj + o);
                cpa16(vlD + (e * VPITCH + o) * 2, vlb + (size_t)e * NTOK + jj + o);
            } else {
                *(uint4*)&VhP[e * VPITCH + o] = make_uint4(0u, 0u, 0u, 0u);
                *(uint4*)&VlP[e * VPITCH + o] = make_uint4(0u, 0u, 0u, 0u);
            }
        }
    };

    // load Q tile (plain loads) + prologue K(0), V(0)->stage0
    {
        const __nv_bfloat16* qsrc = g_qc + ((size_t)bh * NTOK + TTXT + q0) * 192;
        for (int u = tid; u < 128 * 24; u += 128) {
            int r = u / 24, o = (u % 24) * 8;
            *(uint4*)&Qs[r * QPITCH + o] = *(const uint4*)(qsrc + (size_t)r * 192 + o);
        }
    }
    load_k(0);
    load_v(0, 0);
    CP_COMMIT();

    float mrow[2][2], lrow[2][2];
    #pragma unroll
    for (int mt = 0; mt < 2; mt++) { mrow[mt][0] = mrow[mt][1] = -1e30f; lrow[mt][0] = lrow[mt][1] = 0.f; }

    float O[2][8][4];
    #pragma unroll
    for (int mt = 0; mt < 2; mt++)
        #pragma unroll
        for (int nt = 0; nt < 8; nt++)
            #pragma unroll
            for (int j = 0; j < 4; j++) O[mt][nt][j] = 0.f;

    for (int t = 0; t < 17; t++) {
        const int j0 = t * 64;
        CP_WAIT(0);          // K(t), V(t) landed (issued during tile t-1)
        __syncthreads();

        // ---- scores (consume K(t)) ----
        float S[2][8][4];
        #pragma unroll
        for (int mt = 0; mt < 2; mt++)
            #pragma unroll
            for (int nt = 0; nt < 8; nt++)
                #pragma unroll
                for (int j = 0; j < 4; j++) S[mt][nt][j] = 0.f;

        #pragma unroll
        for (int ks = 0; ks < 12; ks++) {
            uint32_t a[2][4];
            ldsm4(a[0], qBase + ks * 32);
            ldsm4(a[1], qBase + 16 * (QPITCH * 2) + ks * 32);
            uint32_t bfr[8][2];
            #pragma unroll
            for (int np = 0; np < 4; np++) {
                uint32_t tmp[4];
                ldsm4(tmp, kBase + np * (16 * QPITCH * 2) + ks * 32);
                bfr[2*np][0]   = tmp[0];
                bfr[2*np][1]   = tmp[1];
                bfr[2*np+1][0] = tmp[2];
                bfr[2*np+1][1] = tmp[3];
            }
            #pragma unroll
            for (int nt = 0; nt < 8; nt++) {
                mma16816(S[0][nt], a[0], bfr[nt]);
                mma16816(S[1][nt], a[1], bfr[nt]);
            }
        }

        // K buffer free; prefetch K(t+1) + V(t+1) into the other V stage
        __syncthreads();
        if (t + 1 < 17) {
            load_k(j0 + 64);
            load_v(j0 + 64, (t + 1) & 1);
            CP_COMMIT();
        }

        // ---- softmax ----
        #pragma unroll
        for (int mt = 0; mt < 2; mt++) {
            #pragma unroll
            for (int nt = 0; nt < 8; nt++) {
                const int key = j0 + nt * 8 + tg * 2;
                const bool v0 = key < NTOK, v1 = key + 1 < NTOK;
                S[mt][nt][0] = v0 ? S[mt][nt][0] * 0.125f : -1e30f;
                S[mt][nt][1] = v1 ? S[mt][nt][1] * 0.125f : -1e30f;
                S[mt][nt][2] = v0 ? S[mt][nt][2] * 0.125f : -1e30f;
                S[mt][nt][3] = v1 ? S[mt][nt][3] * 0.125f : -1e30f;
            }

            float t0 = -1e30f, t1 = -1e30f;
            #pragma unroll
            for (int nt = 0; nt < 8; nt++) {
                t0 = fmaxf(t0, fmaxf(S[mt][nt][0], S[mt][nt][1]));
                t1 = fmaxf(t1, fmaxf(S[mt][nt][2], S[mt][nt][3]));
            }
            t0 = fmaxf(t0, __shfl_xor_sync(0xffffffffu, t0, 1));
            t0 = fmaxf(t0, __shfl_xor_sync(0xffffffffu, t0, 2));
            t1 = fmaxf(t1, __shfl_xor_sync(0xffffffffu, t1, 1));
            t1 = fmaxf(t1, __shfl_xor_sync(0xffffffffu, t1, 2));

            const float mn0 = fmaxf(mrow[mt][0], t0), mn1 = fmaxf(mrow[mt][1], t1);
            const float al0 = __expf(mrow[mt][0] - mn0), al1 = __expf(mrow[mt][1] - mn1);
            mrow[mt][0] = mn0; mrow[mt][1] = mn1;

            float rs0 = 0.f, rs1 = 0.f;
            #pragma unroll
            for (int nt = 0; nt < 8; nt++) {
                S[mt][nt][0] = __expf(S[mt][nt][0] - mn0);
                S[mt][nt][1] = __expf(S[mt][nt][1] - mn0);
                S[mt][nt][2] = __expf(S[mt][nt][2] - mn1);
                S[mt][nt][3] = __expf(S[mt][nt][3] - mn1);
                rs0 += S[mt][nt][0] + S[mt][nt][1];
                rs1 += S[mt][nt][2] + S[mt][nt][3];
            }
            rs0 += __shfl_xor_sync(0xffffffffu, rs0, 1);
            rs0 += __shfl_xor_sync(0xffffffffu, rs0, 2);
            rs1 += __shfl_xor_sync(0xffffffffu, rs1, 1);
            rs1 += __shfl_xor_sync(0xffffffffu, rs1, 2);
            lrow[mt][0] = lrow[mt][0] * al0 + rs0;
            lrow[mt][1] = lrow[mt][1] * al1 + rs1;

            #pragma unroll
            for (int nt = 0; nt < 8; nt++) {
                O[mt][nt][0] *= al0; O[mt][nt][1] *= al0;
                O[mt][nt][2] *= al1; O[mt][nt][3] *= al1;
            }
        }

        // pack P into A-fragments (hi + lo)
        uint32_t ph[2][4][4], pl[2][4][4];
        #pragma unroll
        for (int mt = 0; mt < 2; mt++) {
            #pragma unroll
            for (int ks = 0; ks < 4; ks++) {
                pack_hilo(S[mt][2*ks][0],   S[mt][2*ks][1],   ph[mt][ks][0], pl[mt][ks][0]);
                pack_hilo(S[mt][2*ks][2],   S[mt][2*ks][3],   ph[mt][ks][1], pl[mt][ks][1]);
                pack_hilo(S[mt][2*ks+1][0], S[mt][2*ks+1][1], ph[mt][ks][2], pl[mt][ks][2]);
                pack_hilo(S[mt][2*ks+1][2], S[mt][2*ks+1][3], ph[mt][ks][3], pl[mt][ks][3]);
            }
        }

        // ---- PV: consume V(t) from stage t&1 ----
        const uint32_t vhBase = vhAddr + (t & 1) * VSTG + vfragOff;
        const uint32_t vlBase = vlAddr + (t & 1) * VSTG + vfragOff;
        #pragma unroll
        for (int ks = 0; ks < 4; ks++) {
            uint32_t vh2[8][2], vl2[8][2];
            #pragma unroll
            for (int np = 0; np < 4; np++) {
                uint32_t th[4], tl[4];
                ldsm4(th, vhBase + np * (16 * VPITCH * 2) + ks * 32);
                ldsm4(tl, vlBase + np * (16 * VPITCH * 2) + ks * 32);
                vh2[2*np][0] = th[0]; vh2[2*np][1] = th[1];
                vh2[2*np+1][0] = th[2]; vh2[2*np+1][1] = th[3];
                vl2[2*np][0] = tl[0]; vl2[2*np][1] = tl[1];
                vl2[2*np+1][0] = tl[2]; vl2[2*np+1][1] = tl[3];
            }
            #pragma unroll
            for (int nt = 0; nt < 8; nt++) {
                #pragma unroll
                for (int mt = 0; mt < 2; mt++) {
                    mma16816(O[mt][nt], ph[mt][ks], vh2[nt]);
                    mma16816(O[mt][nt], ph[mt][ks], vl2[nt]);
                    mma16816(O[mt][nt], pl[mt][ks], vh2[nt]);
                }
            }
        }
    }

    // epilogue
    const int b = bh / H_, h = bh - b * H_;
    #pragma unroll
    for (int mt = 0; mt < 2; mt++) {
        const float inv0 = 1.f / lrow[mt][0], inv1 = 1.f / lrow[mt][1];
        const int row0 = b * NTOK + TTXT + q0 + wrow + mt * 16 + g;
        const int row1 = row0 + 8;
        #pragma unroll
        for (int nt = 0; nt < 8; nt++) {
            const int c = h * HD + nt * 8 + tg * 2;
            store_split3(row0, c,     O[mt][nt][0] * inv0);
            store_split3(row0, c + 1, O[mt][nt][1] * inv0);
            store_split3(row1, c,     O[mt][nt][2] * inv1);
            store_split3(row1, c + 1, O[mt][nt][3] * inv1);
        }
    }
}

// ---------------- launch ----------------
extern "C" void kernel_launch(void* const* d_in, const int* in_sizes, int n_in,
                              void* d_out, int out_size)
{
    const float* x      = (const float*)d_in[0];
    const float* qkv_w  = (const float*)d_in[1];
    const float* proj_w = (const float*)d_in[2];
    const float* proj_b = (const float*)d_in[3];
    float* out = (float*)d_out;

    cudaFuncSetAttribute(img_attn_mma_kernel,
                         cudaFuncAttributeMaxDynamicSharedMemorySize, IMG_SMEM2);
    cudaFuncSetAttribute(qkv_gemm_kernel,
                         cudaFuncAttributeMaxDynamicSharedMemorySize, GEMM_SMEM);
    cudaFuncSetAttribute(proj_gemm_kernel,
                         cudaFuncAttributeMaxDynamicSharedMemorySize, GEMM_SMEM);

    split_x_kernel <<<(MPAD*CDIM + 255)/256, 256>>>(x);
    split_w1_kernel<<<(NQKV*CDIM + 255)/256, 256>>>(qkv_w);
    split_w2_kernel<<<(CDIM*CDIM + 255)/256, 256>>>(proj_w);

    qkv_gemm_kernel<<<dim3(NQKV/128, MPAD/128), 128, GEMM_SMEM>>>();

    text_attn_kernel<<<B_*H_, 64>>>();
    img_attn_mma_kernel<<<dim3(SIMG/128, B_*H_), 128, IMG_SMEM2>>>();

    proj_gemm_kernel<<<dim3(CDIM/128, MPAD/128), 128, GEMM_SMEM>>>(proj_b, out);
}

// round 13
// speedup vs baseline: 1.3506x; 1.1157x over previous
#include <cuda_runtime.h>
#include <cuda_bf16.h>
#include <cstdint>

// ---------------- problem constants ----------------
#define B_    8
#define TTXT  40
#define SIMG  1024
#define NTOK  1064
#define CDIM  768
#define H_    12
#define HD    64
#define MROWS (B_*NTOK)       // 8512
#define MPAD  8576            // 67*128
#define KC    (2*CDIM)        // 1536 : compact [hi|lo] K length
#define NQKV  (3*CDIM)        // 2304

// ---------------- device scratch (referenced ONLY from device code) ----------------
__device__ float g_q [B_*H_*NTOK*HD];
__device__ float g_k [B_*H_*NTOK*HD];
__device__ float g_v [B_*H_*NTOK*HD];

// compact [hi|lo] operands (hi = cols 0..767, lo = 768..1535)
__device__ __align__(16) __nv_bfloat16 gxc [MPAD*KC];
__device__ __align__(16) __nv_bfloat16 gw1c[NQKV*KC];
__device__ __align__(16) __nv_bfloat16 gw2c[CDIM*KC];
__device__ __align__(16) __nv_bfloat16 gaoc[MPAD*KC];

__device__ __align__(16) __nv_bfloat16 g_qc [B_*H_*NTOK*128];  // [bh][n][hi64|lo64]
__device__ __align__(16) __nv_bfloat16 g_kc [B_*H_*NTOK*128];  // [bh][n][hi64|lo64]
__device__ __align__(16) __nv_bfloat16 g_vht[B_*H_*HD*NTOK];   // V^T hi: [bh][e][n]
__device__ __align__(16) __nv_bfloat16 g_vlt[B_*H_*HD*NTOK];   // V^T lo

// ---------------- helpers ----------------
__device__ __forceinline__ void pack_hilo(float x, float y, uint32_t& hi, uint32_t& lo)
{
    __nv_bfloat162 h = __floats2bfloat162_rn(x, y);
    float hx = __bfloat162float(h.x), hy = __bfloat162float(h.y);
    __nv_bfloat162 l = __floats2bfloat162_rn(x - hx, y - hy);
    hi = *(uint32_t*)&h;
    lo = *(uint32_t*)&l;
}

// ---------------- split kernels: fp32 -> compact [hi|lo], paired 32-bit stores -----
__global__ __launch_bounds__(256) void split_x_kernel(const float* __restrict__ src)
{
    int i = blockIdx.x * 256 + threadIdx.x;           // pair index
    if (i >= MPAD * (CDIM/2)) return;
    int row = i / (CDIM/2), c = (i - row * (CDIM/2)) * 2;
    float f0 = 0.f, f1 = 0.f;
    if (row < MROWS) {
        float2 v = *(const float2*)(src + (size_t)row * CDIM + c);
        f0 = v.x; f1 = v.y;
    }
    uint32_t hp, lp;
    pack_hilo(f0, f1, hp, lp);
    *(uint32_t*)(gxc + (size_t)row * KC + c)       = hp;
    *(uint32_t*)(gxc + (size_t)row * KC + 768 + c) = lp;
}

__global__ __launch_bounds__(256) void split_w1_kernel(const float* __restrict__ src)
{
    int i = blockIdx.x * 256 + threadIdx.x;
    if (i >= NQKV * (CDIM/2)) return;
    int row = i / (CDIM/2), c = (i - row * (CDIM/2)) * 2;
    float2 v = *(const float2*)(src + (size_t)row * CDIM + c);
    uint32_t hp, lp;
    pack_hilo(v.x, v.y, hp, lp);
    *(uint32_t*)(gw1c + (size_t)row * KC + c)       = hp;
    *(uint32_t*)(gw1c + (size_t)row * KC + 768 + c) = lp;
}

__global__ __launch_bounds__(256) void split_w2_kernel(const float* __restrict__ src)
{
    int i = blockIdx.x * 256 + threadIdx.x;
    if (i >= CDIM * (CDIM/2)) return;
    int row = i / (CDIM/2), c = (i - row * (CDIM/2)) * 2;
    float2 v = *(const float2*)(src + (size_t)row * CDIM + c);
    uint32_t hp, lp;
    pack_hilo(v.x, v.y, hp, lp);
    *(uint32_t*)(gw2c + (size_t)row * KC + c)       = hp;
    *(uint32_t*)(gw2c + (size_t)row * KC + 768 + c) = lp;
}

// ---------------- warp mma + ldmatrix + cp.async ----------------
__device__ __forceinline__ void mma16816(float* d, const uint32_t* a, const uint32_t* b)
{
    asm volatile(
        "mma.sync.aligned.m16n8k16.row.col.f32.bf16.bf16.f32 "
        "{%0,%1,%2,%3}, {%4,%5,%6,%7}, {%8,%9}, {%0,%1,%2,%3};"
        : "+f"(d[0]), "+f"(d[1]), "+f"(d[2]), "+f"(d[3])
        : "r"(a[0]), "r"(a[1]), "r"(a[2]), "r"(a[3]), "r"(b[0]), "r"(b[1]));
}

__device__ __forceinline__ void ldsm4(uint32_t* r, uint32_t addr)
{
    asm volatile("ldmatrix.sync.aligned.m8n8.x4.shared.b16 {%0,%1,%2,%3}, [%4];"
        : "=r"(r[0]), "=r"(r[1]), "=r"(r[2]), "=r"(r[3]) : "r"(addr));
}

__device__ __forceinline__ void cpa16(uint32_t dst, const void* src)
{
    asm volatile("cp.async.cg.shared.global [%0], [%1], 16;" :: "r"(dst), "l"(src));
}
#define CP_COMMIT() asm volatile("cp.async.commit_group;" ::: "memory")
#define CP_WAIT(n)  asm volatile("cp.async.wait_group %0;" :: "n"(n) : "memory")

// D[128,128] = 3-term split GEMM over 72 logical chunks of 32 cols.
// Logical: t<24: Ahi.Bhi ; 24..47: Ahi.Blo ; 48..71: Alo.Bhi.
// Compact source chunk: a = (t<24 ? t : t-24), b = (t<48 ? t : t-48).
// 128 threads, 4 warps 2x2, warp tile 64x64, 3-stage cp.async, one barrier/tile.
#define GSTG  10240                  // bytes per matrix per stage (128*40*2)
#define GEMM_SMEM (6 * GSTG)         // 61440

__device__ __forceinline__ void gemm_main(const __nv_bfloat16* __restrict__ A,
                                          const __nv_bfloat16* __restrict__ B,
                                          int m0, int n0, float acc[4][8][4],
                                          char* gsm)
{
    const int tid  = threadIdx.x;
    const int lane = tid & 31, wid = tid >> 5;
    const int wm = (wid & 1) * 64;
    const int wn = (wid >> 1) * 64;

    const int lr = tid >> 2;          // 0..31
    const int lkb = (tid & 3) * 16;   // byte col offset within chunk: 0,16,32,48

    const uint32_t smA = (uint32_t)__cvta_generic_to_shared(gsm);
    const uint32_t smB = smA + 3 * GSTG;

    const char* Ap = (const char*)(A + (size_t)(m0 + lr) * KC) + lkb;
    const char* Bp = (const char*)(B + (size_t)(n0 + lr) * KC) + lkb;

    const uint32_t dA = smA + lr * 80 + lkb;
    const uint32_t dB = smB + lr * 80 + lkb;

    const uint32_t aBase = smA + (wm + (lane & 15)) * 80 + (lane >> 4) * 16;
    const uint32_t bBase = smB + (wn + ((lane >> 4) * 8) + (lane & 7)) * 80
                               + ((lane >> 3) & 1) * 16;

    const int NKI = 72;

    #pragma unroll
    for (int p = 0; p < 2; p++) {
        const size_t oa = (size_t)p * 64;     // chunks 0,1 are hi/hi for both
        #pragma unroll
        for (int i = 0; i < 4; i++) {
            cpa16(dA + p * GSTG + (32*i) * 80, Ap + oa + (size_t)(32*i) * KC * 2);
            cpa16(dB + p * GSTG + (32*i) * 80, Bp + oa + (size_t)(32*i) * KC * 2);
        }
        CP_COMMIT();
    }

    for (int t = 0; t < NKI; t++) {
        if (t + 1 < NKI) { CP_WAIT(1); } else { CP_WAIT(0); }
        __syncthreads();

        if (t + 2 < NKI) {
            const int tp = t + 2;
            const int s = tp % 3;
            const size_t oa = (size_t)((tp < 24) ? tp : tp - 24) * 64;
            const size_t ob = (size_t)((tp < 48) ? tp : tp - 48) * 64;
            #pragma unroll
            for (int i = 0; i < 4; i++) {
                cpa16(dA + s * GSTG + (32*i) * 80, Ap + oa + (size_t)(32*i) * KC * 2);
                cpa16(dB + s * GSTG + (32*i) * 80, Bp + ob + (size_t)(32*i) * KC * 2);
            }
            CP_COMMIT();
        }

        const uint32_t aB = aBase + (t % 3) * GSTG;
        const uint32_t bB = bBase + (t % 3) * GSTG;
        #pragma unroll
        for (int ks = 0; ks < 2; ks++) {
            uint32_t af[4][4], bfr[8][2];
            #pragma unroll
            for (int mt = 0; mt < 4; mt++)
                ldsm4(af[mt], aB + mt * (16 * 80) + ks * 32);
            #pragma unroll
            for (int np = 0; np < 4; np++) {
                uint32_t tmp[4];
                ldsm4(tmp, bB + np * (16 * 80) + ks * 32);
                bfr[2*np][0]   = tmp[0];
                bfr[2*np][1]   = tmp[1];
                bfr[2*np+1][0] = tmp[2];
                bfr[2*np+1][1] = tmp[3];
            }
            #pragma unroll
            for (int mt = 0; mt < 4; mt++)
                #pragma unroll
                for (int nt = 0; nt < 8; nt++)
                    mma16816(acc[mt][nt], af[mt], bfr[nt]);
        }
    }
}

// ---------------- QKV GEMM: epilogue writes attention-ready layouts ----------------
__global__ __launch_bounds__(128) void qkv_gemm_kernel()
{
    extern __shared__ char gsm[];
    const int n0 = blockIdx.x * 128;
    const int m0 = blockIdx.y * 128;

    float acc[4][8][4] = {};
    gemm_main(gxc, gw1c, m0, n0, acc, gsm);

    const int lane = threadIdx.x & 31, wid = threadIdx.x >> 5;
    const int wm = (wid & 1) * 64, wn = (wid >> 1) * 64;
    const int g = lane >> 2, tg = lane & 3;

    const int s3    = n0 / CDIM;
    const int nrem0 = n0 - s3 * CDIM;

    #pragma unroll
    for (int mt = 0; mt < 4; mt++) {
        #pragma unroll
        for (int nt = 0; nt < 8; nt++) {
            const int col = nrem0 + wn + nt * 8 + tg * 2;
            const int hh = col >> 6, e = col & 63;
            #pragma unroll
            for (int rr = 0; rr < 2; rr++) {
                const int mm = m0 + wm + mt * 16 + g + rr * 8;
                if (mm >= MROWS) continue;
                const int b = mm / NTOK;
                const int n = mm - b * NTOK;
                const size_t idx = (size_t)(b * H_ + hh) * NTOK + n;
                const float v0 = acc[mt][nt][rr * 2 + 0];
                const float v1 = acc[mt][nt][rr * 2 + 1];
                uint32_t hp, lp;
                pack_hilo(v0, v1, hp, lp);
                if (s3 == 0) {
                    *(uint32_t*)(g_qc + idx * 128 + e)      = hp;
                    *(uint32_t*)(g_qc + idx * 128 + 64 + e) = lp;
                    if (n < TTXT) { g_q[idx*HD + e] = v0; g_q[idx*HD + e + 1] = v1; }
                } else if (s3 == 1) {
                    *(uint32_t*)(g_kc + idx * 128 + e)      = hp;
                    *(uint32_t*)(g_kc + idx * 128 + 64 + e) = lp;
                    if (n < TTXT) { g_k[idx*HD + e] = v0; g_k[idx*HD + e + 1] = v1; }
                } else {
                    const __nv_bfloat162 h2 = *(__nv_bfloat162*)&hp;
                    const __nv_bfloat162 l2 = *(__nv_bfloat162*)&lp;
                    const size_t vi = ((size_t)(b * H_ + hh) * HD + e) * NTOK + n;
                    g_vht[vi]        = h2.x;
                    g_vht[vi + NTOK] = h2.y;
                    g_vlt[vi]        = l2.x;
                    g_vlt[vi + NTOK] = l2.y;
                    if (n < TTXT) { g_v[idx*HD + e] = v0; g_v[idx*HD + e + 1] = v1; }
                }
            }
        }
    }
}

// ---------------- proj GEMM kernel ----------------
__global__ __launch_bounds__(128) void proj_gemm_kernel(const float* __restrict__ bias,
                                                        float* __restrict__ out)
{
    extern __shared__ char gsm[];
    const int n0 = blockIdx.x * 128;
    const int m0 = blockIdx.y * 128;

    float acc[4][8][4] = {};
    gemm_main(gaoc, gw2c, m0, n0, acc, gsm);

    const int lane = threadIdx.x & 31, wid = threadIdx.x >> 5;
    const int wm = (wid & 1) * 64, wn = (wid >> 1) * 64;
    const int g = lane >> 2, tg = lane & 3;

    #pragma unroll
    for (int mt = 0; mt < 4; mt++) {
        #pragma unroll
        for (int nt = 0; nt < 8; nt++) {
            const int d = n0 + wn + nt * 8 + tg * 2;
            const float b0 = bias[d], b1 = bias[d + 1];
            #pragma unroll
            for (int rr = 0; rr < 2; rr++) {
                const int m = m0 + wm + mt * 16 + g + rr * 8;
                if (m >= MROWS) continue;
                out[(size_t)m * CDIM + d]     = acc[mt][nt][rr * 2 + 0] + b0;
                out[(size_t)m * CDIM + d + 1] = acc[mt][nt][rr * 2 + 1] + b1;
            }
        }
    }
}

// ---------------- text attention (fp32, tiny; compact gaoc store) ----------------
__global__ __launch_bounds__(64) void text_attn_kernel()
{
    const int bh = blockIdx.x;
    const int b = bh / H_;
    const int h = bh - b * H_;

    __shared__ float Kt[TTXT][HD];
    __shared__ float Vt[TTXT][HD];

    const size_t base = (size_t)(b*H_ + h) * NTOK * HD;
    const float* kbase = g_k + base;
    const float* vbase = g_v + base;

    const int tid = threadIdx.x;
    for (int i = tid; i < TTXT*HD; i += 64) {
        Kt[i / HD][i % HD] = kbase[i];
        Vt[i / HD][i % HD] = vbase[i];
    }
    __syncthreads();

    if (tid < TTXT) {
        const float* qrow = g_q + base + (size_t)tid * HD;
        float qv[HD];
        #pragma unroll
        for (int e = 0; e < HD; e++) qv[e] = qrow[e];

        float sc[TTXT];
        float mx = -1e30f;
        #pragma unroll 4
        for (int s = 0; s < TTXT; s++) {
            float d = 0.f;
            #pragma unroll
            for (int e = 0; e < HD; e++) d += qv[e] * Kt[s][e];
            d *= 0.125f;
            sc[s] = d;
            mx = fmaxf(mx, d);
        }
        float sum = 0.f;
        #pragma unroll
        for (int s = 0; s < TTXT; s++) { sc[s] = __expf(sc[s] - mx); sum += sc[s]; }
        float inv = 1.f / sum;

        const int row = b * NTOK + tid;
        #pragma unroll 2
        for (int e = 0; e < HD; e += 2) {
            float a0 = 0.f, a1 = 0.f;
            #pragma unroll
            for (int s = 0; s < TTXT; s++) {
                a0 += sc[s] * Vt[s][e];
                a1 += sc[s] * Vt[s][e + 1];
            }
            uint32_t hp, lp;
            pack_hilo(a0 * inv, a1 * inv, hp, lp);
            const int c = h * HD + e;
            *(uint32_t*)(gaoc + (size_t)row * KC + c)       = hp;
            *(uint32_t*)(gaoc + (size_t)row * KC + 768 + c) = lp;
        }
    }
}

// ---------------- image attention: mma flash kernel (128-query blocks) ----------------
// smem: Q[128][136] | K[64][136] | Vh[2][64][72] | Vl[2][64][72]
#define QP     136
#define VPITCH 72
#define OFF_K  34816
#define OFF_VH 52224
#define VSTG   9216
#define OFF_VL (OFF_VH + 2*VSTG)     // 70656
#define IMG_SMEM2 (OFF_VL + 2*VSTG)  // 89088

__global__ __launch_bounds__(128) void img_attn_mma_kernel()
{
    extern __shared__ char smx[];
    __nv_bfloat16* Qs = (__nv_bfloat16*)(smx);            // [128][136]
    __nv_bfloat16* Ks = (__nv_bfloat16*)(smx + OFF_K);    // [64][136]

    const int bh = blockIdx.y;
    const int q0 = blockIdx.x * 128;
    const int tid = threadIdx.x;
    const int lane = tid & 31, wid = tid >> 5;
    const int g = lane >> 2, tg = lane & 3;
    const int wrow = wid * 32;            // 32 query rows per warp

    const uint32_t qAddr = (uint32_t)__cvta_generic_to_shared(Qs);
    const uint32_t ksAddr = (uint32_t)__cvta_generic_to_shared(Ks);
    const uint32_t vhAddr = (uint32_t)__cvta_generic_to_shared(smx + OFF_VH);
    const uint32_t vlAddr = (uint32_t)__cvta_generic_to_shared(smx + OFF_VL);

    const uint32_t qBase = qAddr
        + ((wrow + (lane & 15)) * QP + (lane >> 4) * 8) * 2;
    const uint32_t kBase = ksAddr
        + ((((lane >> 4) * 8) + (lane & 7)) * QP + ((lane >> 3) & 1) * 8) * 2;
    const uint32_t vfragOff =
        ((((lane >> 4) * 8) + (lane & 7)) * VPITCH + ((lane >> 3) & 1) * 8) * 2;

    const __nv_bfloat16* qcb = g_qc + ((size_t)bh * NTOK + TTXT + q0) * 128;
    const __nv_bfloat16* kcb = g_kc + (size_t)bh * NTOK * 128;
    const __nv_bfloat16* vhb = g_vht + (size_t)bh * HD * NTOK;
    const __nv_bfloat16* vlb = g_vlt + (size_t)bh * HD * NTOK;

    auto load_k = [&](int jj) {
        for (int u = tid; u < 64 * 16; u += 128) {
            int r = u >> 4, o = (u & 15) * 8;
            if (jj + r < NTOK)
                cpa16(ksAddr + (r * QP + o) * 2, kcb + (size_t)(jj + r) * 128 + o);
            else
                *(uint4*)&Ks[r * QP + o] = make_uint4(0u, 0u, 0u, 0u);
        }
    };
    auto load_v = [&](int jj, int stg) {
        const uint32_t vhD = vhAddr + stg * VSTG;
        const uint32_t vlD = vlAddr + stg * VSTG;
        __nv_bfloat16* VhP = (__nv_bfloat16*)(smx + OFF_VH + stg * VSTG);
        __nv_bfloat16* VlP = (__nv_bfloat16*)(smx + OFF_VL + stg * VSTG);
        for (int u = tid; u < 64 * 8; u += 128) {
            int e = u >> 3, o = (u & 7) * 8;
            if (jj + o + 7 < NTOK) {
                cpa16(vhD + (e * VPITCH + o) * 2, vhb + (size_t)e * NTOK + jj + o);
                cpa16(vlD + (e * VPITCH + o) * 2, vlb + (size_t)e * NTOK + jj + o);
            } else {
                *(uint4*)&VhP[e * VPITCH + o] = make_uint4(0u, 0u, 0u, 0u);
                *(uint4*)&VlP[e * VPITCH + o] = make_uint4(0u, 0u, 0u, 0u);
            }
        }
    };

    // prologue: Q (cp.async), K(0), V(0)->stage0
    for (int u = tid; u < 128 * 16; u += 128) {
        int r = u >> 4, o = (u & 15) * 8;
        cpa16(qAddr + (r * QP + o) * 2, qcb + (size_t)r * 128 + o);
    }
    load_k(0);
    load_v(0, 0);
    CP_COMMIT();

    float mrow[2][2], lrow[2][2];
    #pragma unroll
    for (int mt = 0; mt < 2; mt++) { mrow[mt][0] = mrow[mt][1] = -1e30f; lrow[mt][0] = lrow[mt][1] = 0.f; }

    float O[2][8][4];
    #pragma unroll
    for (int mt = 0; mt < 2; mt++)
        #pragma unroll
        for (int nt = 0; nt < 8; nt++)
            #pragma unroll
            for (int j = 0; j < 4; j++) O[mt][nt][j] = 0.f;

    for (int t = 0; t < 17; t++) {
        const int j0 = t * 64;
        CP_WAIT(0);
        __syncthreads();

        // ---- scores: 12 logical ks chunks; Q map hi,hi,lo / K map hi,lo,hi ----
        float S[2][8][4];
        #pragma unroll
        for (int mt = 0; mt < 2; mt++)
            #pragma unroll
            for (int nt = 0; nt < 8; nt++)
                #pragma unroll
                for (int j = 0; j < 4; j++) S[mt][nt][j] = 0.f;

        #pragma unroll
        for (int ks = 0; ks < 12; ks++) {
            const int qc = (ks < 8) ? (ks & 3) : (ks - 4);   // chunk into [hi0..3|lo0..3]
            const int kc = (ks < 8) ? ks : (ks - 8);
            uint32_t a[2][4];
            ldsm4(a[0], qBase + qc * 32);
            ldsm4(a[1], qBase + 16 * (QP * 2) + qc * 32);
            uint32_t bfr[8][2];
            #pragma unroll
            for (int np = 0; np < 4; np++) {
                uint32_t tmp[4];
                ldsm4(tmp, kBase + np * (16 * QP * 2) + kc * 32);
                bfr[2*np][0]   = tmp[0];
                bfr[2*np][1]   = tmp[1];
                bfr[2*np+1][0] = tmp[2];
                bfr[2*np+1][1] = tmp[3];
            }
            #pragma unroll
            for (int nt = 0; nt < 8; nt++) {
                mma16816(S[0][nt], a[0], bfr[nt]);
                mma16816(S[1][nt], a[1], bfr[nt]);
            }
        }

        // K buffer free; prefetch K(t+1) + V(t+1)
        __syncthreads();
        if (t + 1 < 17) {
            load_k(j0 + 64);
            load_v(j0 + 64, (t + 1) & 1);
            CP_COMMIT();
        }

        // ---- softmax ----
        #pragma unroll
        for (int mt = 0; mt < 2; mt++) {
            #pragma unroll
            for (int nt = 0; nt < 8; nt++) {
                const int key = j0 + nt * 8 + tg * 2;
                const bool v0 = key < NTOK, v1 = key + 1 < NTOK;
                S[mt][nt][0] = v0 ? S[mt][nt][0] * 0.125f : -1e30f;
                S[mt][nt][1] = v1 ? S[mt][nt][1] * 0.125f : -1e30f;
                S[mt][nt][2] = v0 ? S[mt][nt][2] * 0.125f : -1e30f;
                S[mt][nt][3] = v1 ? S[mt][nt][3] * 0.125f : -1e30f;
            }

            float t0 = -1e30f, t1 = -1e30f;
            #pragma unroll
            for (int nt = 0; nt < 8; nt++) {
                t0 = fmaxf(t0, fmaxf(S[mt][nt][0], S[mt][nt][1]));
                t1 = fmaxf(t1, fmaxf(S[mt][nt][2], S[mt][nt][3]));
            }
            t0 = fmaxf(t0, __shfl_xor_sync(0xffffffffu, t0, 1));
            t0 = fmaxf(t0, __shfl_xor_sync(0xffffffffu, t0, 2));
            t1 = fmaxf(t1, __shfl_xor_sync(0xffffffffu, t1, 1));
            t1 = fmaxf(t1, __shfl_xor_sync(0xffffffffu, t1, 2));

            const float mn0 = fmaxf(mrow[mt][0], t0), mn1 = fmaxf(mrow[mt][1], t1);
            const float al0 = __expf(mrow[mt][0] - mn0), al1 = __expf(mrow[mt][1] - mn1);
            mrow[mt][0] = mn0; mrow[mt][1] = mn1;

            float rs0 = 0.f, rs1 = 0.f;
            #pragma unroll
            for (int nt = 0; nt < 8; nt++) {
                S[mt][nt][0] = __expf(S[mt][nt][0] - mn0);
                S[mt][nt][1] = __expf(S[mt][nt][1] - mn0);
                S[mt][nt][2] = __expf(S[mt][nt][2] - mn1);
                S[mt][nt][3] = __expf(S[mt][nt][3] - mn1);
                rs0 += S[mt][nt][0] + S[mt][nt][1];
                rs1 += S[mt][nt][2] + S[mt][nt][3];
            }
            rs0 += __shfl_xor_sync(0xffffffffu, rs0, 1);
            rs0 += __shfl_xor_sync(0xffffffffu, rs0, 2);
            rs1 += __shfl_xor_sync(0xffffffffu, rs1, 1);
            rs1 += __shfl_xor_sync(0xffffffffu, rs1, 2);
            lrow[mt][0] = lrow[mt][0] * al0 + rs0;
            lrow[mt][1] = lrow[mt][1] * al1 + rs1;

            #pragma unroll
            for (int nt = 0; nt < 8; nt++) {
                O[mt][nt][0] *= al0; O[mt][nt][1] *= al0;
                O[mt][nt][2] *= al1; O[mt][nt][3] *= al1;
            }
        }

        // pack P into A-fragments (hi + lo)
        uint32_t ph[2][4][4], pl[2][4][4];
        #pragma unroll
        for (int mt = 0; mt < 2; mt++) {
            #pragma unroll
            for (int ks = 0; ks < 4; ks++) {
                pack_hilo(S[mt][2*ks][0],   S[mt][2*ks][1],   ph[mt][ks][0], pl[mt][ks][0]);
                pack_hilo(S[mt][2*ks][2],   S[mt][2*ks][3],   ph[mt][ks][1], pl[mt][ks][1]);
                pack_hilo(S[mt][2*ks+1][0], S[mt][2*ks+1][1], ph[mt][ks][2], pl[mt][ks][2]);
                pack_hilo(S[mt][2*ks+1][2], S[mt][2*ks+1][3], ph[mt][ks][3], pl[mt][ks][3]);
            }
        }

        // ---- PV: consume V(t) from stage t&1 ----
        const uint32_t vhBase = vhAddr + (t & 1) * VSTG + vfragOff;
        const uint32_t vlBase = vlAddr + (t & 1) * VSTG + vfragOff;
        #pragma unroll
        for (int ks = 0; ks < 4; ks++) {
            uint32_t vh2[8][2], vl2[8][2];
            #pragma unroll
            for (int np = 0; np < 4; np++) {
                uint32_t th[4], tl[4];
                ldsm4(th, vhBase + np * (16 * VPITCH * 2) + ks * 32);
                ldsm4(tl, vlBase + np * (16 * VPITCH * 2) + ks * 32);
                vh2[2*np][0] = th[0]; vh2[2*np][1] = th[1];
                vh2[2*np+1][0] = th[2]; vh2[2*np+1][1] = th[3];
                vl2[2*np][0] = tl[0]; vl2[2*np][1] = tl[1];
                vl2[2*np+1][0] = tl[2]; vl2[2*np+1][1] = tl[3];
            }
            #pragma unroll
            for (int nt = 0; nt < 8; nt++) {
                #pragma unroll
                for (int mt = 0; mt < 2; mt++) {
                    mma16816(O[mt][nt], ph[mt][ks], vh2[nt]);
                    mma16816(O[mt][nt], ph[mt][ks], vl2[nt]);
                    mma16816(O[mt][nt], pl[mt][ks], vh2[nt]);
                }
            }
        }
    }

    // epilogue (compact packed stores)
    const int b = bh / H_, h = bh - b * H_;
    #pragma unroll
    for (int mt = 0; mt < 2; mt++) {
        const float inv0 = 1.f / lrow[mt][0], inv1 = 1.f / lrow[mt][1];
        const int row0 = b * NTOK + TTXT + q0 + wrow + mt * 16 + g;
        const int row1 = row0 + 8;
        #pragma unroll
        for (int nt = 0; nt < 8; nt++) {
            const int c = h * HD + nt * 8 + tg * 2;
            uint32_t hp, lp;
            pack_hilo(O[mt][nt][0] * inv0, O[mt][nt][1] * inv0, hp, lp);
            *(uint32_t*)(gaoc + (size_t)row0 * KC + c)       = hp;
            *(uint32_t*)(gaoc + (size_t)row0 * KC + 768 + c) = lp;
            pack_hilo(O[mt][nt][2] * inv1, O[mt][nt][3] * inv1, hp, lp);
            *(uint32_t*)(gaoc + (size_t)row1 * KC + c)       = hp;
            *(uint32_t*)(gaoc + (size_t)row1 * KC + 768 + c) = lp;
        }
    }
}

// ---------------- launch ----------------
extern "C" void kernel_launch(void* const* d_in, const int* in_sizes, int n_in,
                              void* d_out, int out_size)
{
    const float* x      = (const float*)d_in[0];
    const float* qkv_w  = (const float*)d_in[1];
    const float* proj_w = (const float*)d_in[2];
    const float* proj_b = (const float*)d_in[3];
    float* out = (float*)d_out;

    cudaFuncSetAttribute(img_attn_mma_kernel,
                         cudaFuncAttributeMaxDynamicSharedMemorySize, IMG_SMEM2);
    cudaFuncSetAttribute(qkv_gemm_kernel,
                         cudaFuncAttributeMaxDynamicSharedMemorySize, GEMM_SMEM);
    cudaFuncSetAttribute(proj_gemm_kernel,
                         cudaFuncAttributeMaxDynamicSharedMemorySize, GEMM_SMEM);

    split_x_kernel <<<(MPAD*(CDIM/2) + 255)/256, 256>>>(x);
    split_w1_kernel<<<(NQKV*(CDIM/2) + 255)/256, 256>>>(qkv_w);
    split_w2_kernel<<<(CDIM*(CDIM/2) + 255)/256, 256>>>(proj_w);

    qkv_gemm_kernel<<<dim3(NQKV/128, MPAD/128), 128, GEMM_SMEM>>>();

    text_attn_kernel<<<B_*H_, 64>>>();
    img_attn_mma_kernel<<<dim3(SIMG/128, B_*H_), 128, IMG_SMEM2>>>();

    proj_gemm_kernel<<<dim3(CDIM/128, MPAD/128), 128, GEMM_SMEM>>>(proj_b, out);
}

// round 14
// speedup vs baseline: 1.4312x; 1.0597x over previous
#include <cuda_runtime.h>
#include <cuda_bf16.h>
#include <cstdint>

// ---------------- problem constants ----------------
#define B_    8
#define TTXT  40
#define SIMG  1024
#define NTOK  1064
#define CDIM  768
#define H_    12
#define HD    64
#define MROWS (B_*NTOK)       // 8512
#define MPAD  8576            // 67*128
#define KC    (2*CDIM)        // 1536 : compact [hi|lo] K length
#define NQKV  (3*CDIM)        // 2304

// ---------------- device scratch (referenced ONLY from device code) ----------------
__device__ float g_q [B_*H_*NTOK*HD];
__device__ float g_k [B_*H_*NTOK*HD];
__device__ float g_v [B_*H_*NTOK*HD];

__device__ __align__(16) __nv_bfloat16 gxc [MPAD*KC];
__device__ __align__(16) __nv_bfloat16 gw1c[NQKV*KC];
__device__ __align__(16) __nv_bfloat16 gw2c[CDIM*KC];
__device__ __align__(16) __nv_bfloat16 gaoc[MPAD*KC];

__device__ __align__(16) __nv_bfloat16 g_qc [B_*H_*NTOK*128];  // [bh][n][hi64|lo64]
__device__ __align__(16) __nv_bfloat16 g_kc [B_*H_*NTOK*128];  // [bh][n][hi64|lo64]
__device__ __align__(16) __nv_bfloat16 g_vht[B_*H_*HD*NTOK];   // V^T hi: [bh][e][n]
__device__ __align__(16) __nv_bfloat16 g_vlt[B_*H_*HD*NTOK];   // V^T lo

// ---------------- helpers ----------------
__device__ __forceinline__ void pack_hilo(float x, float y, uint32_t& hi, uint32_t& lo)
{
    __nv_bfloat162 h = __floats2bfloat162_rn(x, y);
    float hx = __bfloat162float(h.x), hy = __bfloat162float(h.y);
    __nv_bfloat162 l = __floats2bfloat162_rn(x - hx, y - hy);
    hi = *(uint32_t*)&h;
    lo = *(uint32_t*)&l;
}

// ---------------- split kernels ----------------
__global__ __launch_bounds__(256) void split_x_kernel(const float* __restrict__ src)
{
    int i = blockIdx.x * 256 + threadIdx.x;
    if (i >= MPAD * (CDIM/2)) return;
    int row = i / (CDIM/2), c = (i - row * (CDIM/2)) * 2;
    float f0 = 0.f, f1 = 0.f;
    if (row < MROWS) {
        float2 v = *(const float2*)(src + (size_t)row * CDIM + c);
        f0 = v.x; f1 = v.y;
    }
    uint32_t hp, lp;
    pack_hilo(f0, f1, hp, lp);
    *(uint32_t*)(gxc + (size_t)row * KC + c)       = hp;
    *(uint32_t*)(gxc + (size_t)row * KC + 768 + c) = lp;
}

// both weights in one launch: rows [0,2304) -> gw1c, [2304,3072) -> gw2c
__global__ __launch_bounds__(256) void split_w_kernel(const float* __restrict__ w1,
                                                      const float* __restrict__ w2)
{
    int i = blockIdx.x * 256 + threadIdx.x;
    if (i >= (NQKV + CDIM) * (CDIM/2)) return;
    int row = i / (CDIM/2), c = (i - row * (CDIM/2)) * 2;
    const float* src;
    __nv_bfloat16* dst;
    int r;
    if (row < NQKV) { src = w1; dst = gw1c; r = row; }
    else            { src = w2; dst = gw2c; r = row - NQKV; }
    float2 v = *(const float2*)(src + (size_t)r * CDIM + c);
    uint32_t hp, lp;
    pack_hilo(v.x, v.y, hp, lp);
    *(uint32_t*)(dst + (size_t)r * KC + c)       = hp;
    *(uint32_t*)(dst + (size_t)r * KC + 768 + c) = lp;
}

// ---------------- warp mma + ldmatrix + cp.async ----------------
__device__ __forceinline__ void mma16816(float* d, const uint32_t* a, const uint32_t* b)
{
    asm volatile(
        "mma.sync.aligned.m16n8k16.row.col.f32.bf16.bf16.f32 "
        "{%0,%1,%2,%3}, {%4,%5,%6,%7}, {%8,%9}, {%0,%1,%2,%3};"
        : "+f"(d[0]), "+f"(d[1]), "+f"(d[2]), "+f"(d[3])
        : "r"(a[0]), "r"(a[1]), "r"(a[2]), "r"(a[3]), "r"(b[0]), "r"(b[1]));
}

__device__ __forceinline__ void ldsm4(uint32_t* r, uint32_t addr)
{
    asm volatile("ldmatrix.sync.aligned.m8n8.x4.shared.b16 {%0,%1,%2,%3}, [%4];"
        : "=r"(r[0]), "=r"(r[1]), "=r"(r[2]), "=r"(r[3]) : "r"(addr));
}

__device__ __forceinline__ void cpa16(uint32_t dst, const void* src)
{
    asm volatile("cp.async.cg.shared.global [%0], [%1], 16;" :: "r"(dst), "l"(src));
}
#define CP_COMMIT() asm volatile("cp.async.commit_group;" ::: "memory")
#define CP_WAIT(n)  asm volatile("cp.async.wait_group %0;" :: "n"(n) : "memory")

// D[128,128], 3-term split GEMM, term-grouped: 24 chunk iterations; per chunk
// load {Ah, Al, Bh, Bl} once and issue Ah.Bh + Ah.Bl + Al.Bh with fragment reuse.
// 128 threads, warp tile 64x64, 2-stage cp.async pipeline, one barrier/chunk.
#define CSTG  10240                  // bytes per matrix-chunk (128 rows x 80B pitch)
#define GSTG  (4*CSTG)               // stage = Ah|Al|Bh|Bl
#define GEMM_SMEM (2*GSTG)           // 81920

__device__ __forceinline__ void gemm_main(const __nv_bfloat16* __restrict__ A,
                                          const __nv_bfloat16* __restrict__ B,
                                          int m0, int n0, float acc[4][8][4],
                                          char* gsm)
{
    const int tid  = threadIdx.x;
    const int lane = tid & 31, wid = tid >> 5;
    const int wm = (wid & 1) * 64;
    const int wn = (wid >> 1) * 64;

    const int lr = tid >> 2;          // 0..31
    const int lkb = (tid & 3) * 16;   // byte col offset within chunk: 0,16,32,48

    const uint32_t sm0 = (uint32_t)__cvta_generic_to_shared(gsm);

    const char* Ap = (const char*)(A + (size_t)(m0 + lr) * KC) + lkb;
    const char* Bp = (const char*)(B + (size_t)(n0 + lr) * KC) + lkb;

    const uint32_t d0 = sm0 + lr * 80 + lkb;

    // fragment bases within a matrix-chunk region
    const uint32_t aOff = ((wm + (lane & 15)) * 80 + (lane >> 4) * 16);
    const uint32_t bOff = ((wn + ((lane >> 4) * 8) + (lane & 7)) * 80
                           + ((lane >> 3) & 1) * 16);

    const int NKI = 24;

    // chunk loader: chunk c -> stage s
    auto load_chunk = [&](int c, int s) {
        const uint32_t base = d0 + s * GSTG;
        const size_t oh = (size_t)c * 64;          // hi bytes
        const size_t ol = 1536 + (size_t)c * 64;   // lo bytes
        #pragma unroll
        for (int i = 0; i < 4; i++) {
            const size_t rs = (size_t)(32*i) * KC * 2;
            cpa16(base            + (32*i) * 80, Ap + oh + rs);
            cpa16(base + CSTG     + (32*i) * 80, Ap + ol + rs);
            cpa16(base + 2*CSTG   + (32*i) * 80, Bp + oh + rs);
            cpa16(base + 3*CSTG   + (32*i) * 80, Bp + ol + rs);
        }
        CP_COMMIT();
    };

    load_chunk(0, 0);

    for (int t = 0; t < NKI; t++) {
        CP_WAIT(0);
        __syncthreads();
        if (t + 1 < NKI) load_chunk(t + 1, (t + 1) & 1);

        const uint32_t sb = sm0 + (t & 1) * GSTG;
        #pragma unroll
        for (int ks = 0; ks < 2; ks++) {
            const uint32_t ko = ks * 32;
            uint32_t ah[4][4], al[4][4], bh[8][2], bl[8][2];
            #pragma unroll
            for (int mt = 0; mt < 4; mt++)
                ldsm4(ah[mt], sb + aOff + mt * (16 * 80) + ko);
            #pragma unroll
            for (int np = 0; np < 4; np++) {
                uint32_t tmp[4];
                ldsm4(tmp, sb + 2*CSTG + bOff + np * (16 * 80) + ko);
                bh[2*np][0] = tmp[0]; bh[2*np][1] = tmp[1];
                bh[2*np+1][0] = tmp[2]; bh[2*np+1][1] = tmp[3];
            }
            #pragma unroll
            for (int mt = 0; mt < 4; mt++)
                #pragma unroll
                for (int nt = 0; nt < 8; nt++)
                    mma16816(acc[mt][nt], ah[mt], bh[nt]);

            #pragma unroll
            for (int np = 0; np < 4; np++) {
                uint32_t tmp[4];
                ldsm4(tmp, sb + 3*CSTG + bOff + np * (16 * 80) + ko);
                bl[2*np][0] = tmp[0]; bl[2*np][1] = tmp[1];
                bl[2*np+1][0] = tmp[2]; bl[2*np+1][1] = tmp[3];
            }
            #pragma unroll
            for (int mt = 0; mt < 4; mt++)
                #pragma unroll
                for (int nt = 0; nt < 8; nt++)
                    mma16816(acc[mt][nt], ah[mt], bl[nt]);

            #pragma unroll
            for (int mt = 0; mt < 4; mt++)
                ldsm4(al[mt], sb + CSTG + aOff + mt * (16 * 80) + ko);
            #pragma unroll
            for (int mt = 0; mt < 4; mt++)
                #pragma unroll
                for (int nt = 0; nt < 8; nt++)
                    mma16816(acc[mt][nt], al[mt], bh[nt]);
        }
    }
}

// ---------------- QKV GEMM: epilogue writes attention-ready layouts ----------------
__global__ __launch_bounds__(128) void qkv_gemm_kernel()
{
    extern __shared__ char gsm[];
    const int n0 = blockIdx.x * 128;
    const int m0 = blockIdx.y * 128;

    float acc[4][8][4] = {};
    gemm_main(gxc, gw1c, m0, n0, acc, gsm);

    const int lane = threadIdx.x & 31, wid = threadIdx.x >> 5;
    const int wm = (wid & 1) * 64, wn = (wid >> 1) * 64;
    const int g = lane >> 2, tg = lane & 3;

    const int s3    = n0 / CDIM;
    const int nrem0 = n0 - s3 * CDIM;

    #pragma unroll
    for (int mt = 0; mt < 4; mt++) {
        #pragma unroll
        for (int nt = 0; nt < 8; nt++) {
            const int col = nrem0 + wn + nt * 8 + tg * 2;
            const int hh = col >> 6, e = col & 63;
            #pragma unroll
            for (int rr = 0; rr < 2; rr++) {
                const int mm = m0 + wm + mt * 16 + g + rr * 8;
                if (mm >= MROWS) continue;
                const int b = mm / NTOK;
                const int n = mm - b * NTOK;
                const size_t idx = (size_t)(b * H_ + hh) * NTOK + n;
                const float v0 = acc[mt][nt][rr * 2 + 0];
                const float v1 = acc[mt][nt][rr * 2 + 1];
                uint32_t hp, lp;
                pack_hilo(v0, v1, hp, lp);
                if (s3 == 0) {
                    *(uint32_t*)(g_qc + idx * 128 + e)      = hp;
                    *(uint32_t*)(g_qc + idx * 128 + 64 + e) = lp;
                    if (n < TTXT) { g_q[idx*HD + e] = v0; g_q[idx*HD + e + 1] = v1; }
                } else if (s3 == 1) {
                    *(uint32_t*)(g_kc + idx * 128 + e)      = hp;
                    *(uint32_t*)(g_kc + idx * 128 + 64 + e) = lp;
                    if (n < TTXT) { g_k[idx*HD + e] = v0; g_k[idx*HD + e + 1] = v1; }
                } else {
                    const __nv_bfloat162 h2 = *(__nv_bfloat162*)&hp;
                    const __nv_bfloat162 l2 = *(__nv_bfloat162*)&lp;
                    const size_t vi = ((size_t)(b * H_ + hh) * HD + e) * NTOK + n;
                    g_vht[vi]        = h2.x;
                    g_vht[vi + NTOK] = h2.y;
                    g_vlt[vi]        = l2.x;
                    g_vlt[vi + NTOK] = l2.y;
                    if (n < TTXT) { g_v[idx*HD + e] = v0; g_v[idx*HD + e + 1] = v1; }
                }
            }
        }
    }
}

// ---------------- proj GEMM kernel ----------------
__global__ __launch_bounds__(128) void proj_gemm_kernel(const float* __restrict__ bias,
                                                        float* __restrict__ out)
{
    extern __shared__ char gsm[];
    const int n0 = blockIdx.x * 128;
    const int m0 = blockIdx.y * 128;

    float acc[4][8][4] = {};
    gemm_main(gaoc, gw2c, m0, n0, acc, gsm);

    const int lane = threadIdx.x & 31, wid = threadIdx.x >> 5;
    const int wm = (wid & 1) * 64, wn = (wid >> 1) * 64;
    const int g = lane >> 2, tg = lane & 3;

    #pragma unroll
    for (int mt = 0; mt < 4; mt++) {
        #pragma unroll
        for (int nt = 0; nt < 8; nt++) {
            const int d = n0 + wn + nt * 8 + tg * 2;
            const float b0 = bias[d], b1 = bias[d + 1];
            #pragma unroll
            for (int rr = 0; rr < 2; rr++) {
                const int m = m0 + wm + mt * 16 + g + rr * 8;
                if (m >= MROWS) continue;
                out[(size_t)m * CDIM + d]     = acc[mt][nt][rr * 2 + 0] + b0;
                out[(size_t)m * CDIM + d + 1] = acc[mt][nt][rr * 2 + 1] + b1;
            }
        }
    }
}

// ---------------- text attention (fp32, tiny; compact gaoc store) ----------------
__global__ __launch_bounds__(64) void text_attn_kernel()
{
    const int bh = blockIdx.x;
    const int b = bh / H_;
    const int h = bh - b * H_;

    __shared__ float Kt[TTXT][HD];
    __shared__ float Vt[TTXT][HD];

    const size_t base = (size_t)(b*H_ + h) * NTOK * HD;
    const float* kbase = g_k + base;
    const float* vbase = g_v + base;

    const int tid = threadIdx.x;
    for (int i = tid; i < TTXT*HD; i += 64) {
        Kt[i / HD][i % HD] = kbase[i];
        Vt[i / HD][i % HD] = vbase[i];
    }
    __syncthreads();

    if (tid < TTXT) {
        const float* qrow = g_q + base + (size_t)tid * HD;
        float qv[HD];
        #pragma unroll
        for (int e = 0; e < HD; e++) qv[e] = qrow[e];

        float sc[TTXT];
        float mx = -1e30f;
        #pragma unroll 4
        for (int s = 0; s < TTXT; s++) {
            float d = 0.f;
            #pragma unroll
            for (int e = 0; e < HD; e++) d += qv[e] * Kt[s][e];
            d *= 0.125f;
            sc[s] = d;
            mx = fmaxf(mx, d);
        }
        float sum = 0.f;
        #pragma unroll
        for (int s = 0; s < TTXT; s++) { sc[s] = __expf(sc[s] - mx); sum += sc[s]; }
        float inv = 1.f / sum;

        const int row = b * NTOK + tid;
        #pragma unroll 2
        for (int e = 0; e < HD; e += 2) {
            float a0 = 0.f, a1 = 0.f;
            #pragma unroll
            for (int s = 0; s < TTXT; s++) {
                a0 += sc[s] * Vt[s][e];
                a1 += sc[s] * Vt[s][e + 1];
            }
            uint32_t hp, lp;
            pack_hilo(a0 * inv, a1 * inv, hp, lp);
            const int c = h * HD + e;
            *(uint32_t*)(gaoc + (size_t)row * KC + c)       = hp;
            *(uint32_t*)(gaoc + (size_t)row * KC + 768 + c) = lp;
        }
    }
}

// ---------------- image attention: mma flash kernel (128-query blocks) ----------------
// fixed-max softmax (M=20): p = exp(s*0.125 - 20); no online rescale.
#define QP     136
#define VPITCH 72
#define OFF_K  34816
#define OFF_VH 52224
#define VSTG   9216
#define OFF_VL (OFF_VH + 2*VSTG)     // 70656
#define IMG_SMEM2 (OFF_VL + 2*VSTG)  // 89088
#define SMAX   20.0f

__global__ __launch_bounds__(128) void img_attn_mma_kernel()
{
    extern __shared__ char smx[];
    __nv_bfloat16* Qs = (__nv_bfloat16*)(smx);            // [128][136]
    __nv_bfloat16* Ks = (__nv_bfloat16*)(smx + OFF_K);    // [64][136]

    const int bh = blockIdx.y;
    const int q0 = blockIdx.x * 128;
    const int tid = threadIdx.x;
    const int lane = tid & 31, wid = tid >> 5;
    const int g = lane >> 2, tg = lane & 3;
    const int wrow = wid * 32;

    const uint32_t qAddr = (uint32_t)__cvta_generic_to_shared(Qs);
    const uint32_t ksAddr = (uint32_t)__cvta_generic_to_shared(Ks);
    const uint32_t vhAddr = (uint32_t)__cvta_generic_to_shared(smx + OFF_VH);
    const uint32_t vlAddr = (uint32_t)__cvta_generic_to_shared(smx + OFF_VL);

    const uint32_t qBase = qAddr
        + ((wrow + (lane & 15)) * QP + (lane >> 4) * 8) * 2;
    const uint32_t kBase = ksAddr
        + ((((lane >> 4) * 8) + (lane & 7)) * QP + ((lane >> 3) & 1) * 8) * 2;
    const uint32_t vfragOff =
        ((((lane >> 4) * 8) + (lane & 7)) * VPITCH + ((lane >> 3) & 1) * 8) * 2;

    const __nv_bfloat16* qcb = g_qc + ((size_t)bh * NTOK + TTXT + q0) * 128;
    const __nv_bfloat16* kcb = g_kc + (size_t)bh * NTOK * 128;
    const __nv_bfloat16* vhb = g_vht + (size_t)bh * HD * NTOK;
    const __nv_bfloat16* vlb = g_vlt + (size_t)bh * HD * NTOK;

    auto load_k = [&](int jj) {
        for (int u = tid; u < 64 * 16; u += 128) {
            int r = u >> 4, o = (u & 15) * 8;
            if (jj + r < NTOK)
                cpa16(ksAddr + (r * QP + o) * 2, kcb + (size_t)(jj + r) * 128 + o);
            else
                *(uint4*)&Ks[r * QP + o] = make_uint4(0u, 0u, 0u, 0u);
        }
    };
    auto load_v = [&](int jj, int stg) {
        const uint32_t vhD = vhAddr + stg * VSTG;
        const uint32_t vlD = vlAddr + stg * VSTG;
        __nv_bfloat16* VhP = (__nv_bfloat16*)(smx + OFF_VH + stg * VSTG);
        __nv_bfloat16* VlP = (__nv_bfloat16*)(smx + OFF_VL + stg * VSTG);
        for (int u = tid; u < 64 * 8; u += 128) {
            int e = u >> 3, o = (u & 7) * 8;
            if (jj + o + 7 < NTOK) {
                cpa16(vhD + (e * VPITCH + o) * 2, vhb + (size_t)e * NTOK + jj + o);
                cpa16(vlD + (e * VPITCH + o) * 2, vlb + (size_t)e * NTOK + jj + o);
            } else {
                *(uint4*)&VhP[e * VPITCH + o] = make_uint4(0u, 0u, 0u, 0u);
                *(uint4*)&VlP[e * VPITCH + o] = make_uint4(0u, 0u, 0u, 0u);
            }
        }
    };

    // prologue
    for (int u = tid; u < 128 * 16; u += 128) {
        int r = u >> 4, o = (u & 15) * 8;
        cpa16(qAddr + (r * QP + o) * 2, qcb + (size_t)r * 128 + o);
    }
    load_k(0);
    load_v(0, 0);
    CP_COMMIT();

    float lsum[2][2] = {{0.f, 0.f}, {0.f, 0.f}};   // per-lane partial row sums
    float O[2][8][4];
    #pragma unroll
    for (int mt = 0; mt < 2; mt++)
        #pragma unroll
        for (int nt = 0; nt < 8; nt++)
            #pragma unroll
            for (int j = 0; j < 4; j++) O[mt][nt][j] = 0.f;

    for (int t = 0; t < 17; t++) {
        const int j0 = t * 64;
        CP_WAIT(0);
        __syncthreads();

        // ---- scores ----
        float S[2][8][4];
        #pragma unroll
        for (int mt = 0; mt < 2; mt++)
            #pragma unroll
            for (int nt = 0; nt < 8; nt++)
                #pragma unroll
                for (int j = 0; j < 4; j++) S[mt][nt][j] = 0.f;

        #pragma unroll
        for (int ks = 0; ks < 12; ks++) {
            const int qc = (ks < 8) ? (ks & 3) : (ks - 4);
            const int kc = (ks < 8) ? ks : (ks - 8);
            uint32_t a[2][4];
            ldsm4(a[0], qBase + qc * 32);
            ldsm4(a[1], qBase + 16 * (QP * 2) + qc * 32);
            uint32_t bfr[8][2];
            #pragma unroll
            for (int np = 0; np < 4; np++) {
                uint32_t tmp[4];
                ldsm4(tmp, kBase + np * (16 * QP * 2) + kc * 32);
                bfr[2*np][0]   = tmp[0];
                bfr[2*np][1]   = tmp[1];
                bfr[2*np+1][0] = tmp[2];
                bfr[2*np+1][1] = tmp[3];
            }
            #pragma unroll
            for (int nt = 0; nt < 8; nt++) {
                mma16816(S[0][nt], a[0], bfr[nt]);
                mma16816(S[1][nt], a[1], bfr[nt]);
            }
        }

        // K buffer free; prefetch K(t+1) + V(t+1)
        __syncthreads();
        if (t + 1 < 17) {
            load_k(j0 + 64);
            load_v(j0 + 64, (t + 1) & 1);
            CP_COMMIT();
        }

        // ---- fixed-max softmax: p = exp(s*0.125 - 20), masked -> 0 ----
        #pragma unroll
        for (int mt = 0; mt < 2; mt++) {
            #pragma unroll
            for (int nt = 0; nt < 8; nt++) {
                const int key = j0 + nt * 8 + tg * 2;
                const bool v0 = key < NTOK, v1 = key + 1 < NTOK;
                S[mt][nt][0] = v0 ? __expf(fmaf(S[mt][nt][0], 0.125f, -SMAX)) : 0.f;
                S[mt][nt][1] = v1 ? __expf(fmaf(S[mt][nt][1], 0.125f, -SMAX)) : 0.f;
                S[mt][nt][2] = v0 ? __expf(fmaf(S[mt][nt][2], 0.125f, -SMAX)) : 0.f;
                S[mt][nt][3] = v1 ? __expf(fmaf(S[mt][nt][3], 0.125f, -SMAX)) : 0.f;
                lsum[mt][0] += S[mt][nt][0] + S[mt][nt][1];
                lsum[mt][1] += S[mt][nt][2] + S[mt][nt][3];
            }
        }

        // pack P into A-fragments (hi + lo)
        uint32_t ph[2][4][4], pl[2][4][4];
        #pragma unroll
        for (int mt = 0; mt < 2; mt++) {
            #pragma unroll
            for (int ks = 0; ks < 4; ks++) {
                pack_hilo(S[mt][2*ks][0],   S[mt][2*ks][1],   ph[mt][ks][0], pl[mt][ks][0]);
                pack_hilo(S[mt][2*ks][2],   S[mt][2*ks][3],   ph[mt][ks][1], pl[mt][ks][1]);
                pack_hilo(S[mt][2*ks+1][0], S[mt][2*ks+1][1], ph[mt][ks][2], pl[mt][ks][2]);
                pack_hilo(S[mt][2*ks+1][2], S[mt][2*ks+1][3], ph[mt][ks][3], pl[mt][ks][3]);
            }
        }

        // ---- PV: consume V(t) from stage t&1 ----
        const uint32_t vhBase = vhAddr + (t & 1) * VSTG + vfragOff;
        const uint32_t vlBase = vlAddr + (t & 1) * VSTG + vfragOff;
        #pragma unroll
        for (int ks = 0; ks < 4; ks++) {
            uint32_t vh2[8][2], vl2[8][2];
            #pragma unroll
            for (int np = 0; np < 4; np++) {
                uint32_t th[4], tl[4];
                ldsm4(th, vhBase + np * (16 * VPITCH * 2) + ks * 32);
                ldsm4(tl, vlBase + np * (16 * VPITCH * 2) + ks * 32);
                vh2[2*np][0] = th[0]; vh2[2*np][1] = th[1];
                vh2[2*np+1][0] = th[2]; vh2[2*np+1][1] = th[3];
                vl2[2*np][0] = tl[0]; vl2[2*np][1] = tl[1];
                vl2[2*np+1][0] = tl[2]; vl2[2*np+1][1] = tl[3];
            }
            #pragma unroll
            for (int nt = 0; nt < 8; nt++) {
                #pragma unroll
                for (int mt = 0; mt < 2; mt++) {
                    mma16816(O[mt][nt], ph[mt][ks], vh2[nt]);
                    mma16816(O[mt][nt], ph[mt][ks], vl2[nt]);
                    mma16816(O[mt][nt], pl[mt][ks], vh2[nt]);
                }
            }
        }
    }

    // final row-sum reduction (once) + epilogue
    const int b = bh / H_, h = bh - b * H_;
    #pragma unroll
    for (int mt = 0; mt < 2; mt++) {
        float r0 = lsum[mt][0], r1 = lsum[mt][1];
        r0 += __shfl_xor_sync(0xffffffffu, r0, 1);
        r0 += __shfl_xor_sync(0xffffffffu, r0, 2);
        r1 += __shfl_xor_sync(0xffffffffu, r1, 1);
        r1 += __shfl_xor_sync(0xffffffffu, r1, 2);
        const float inv0 = 1.f / r0, inv1 = 1.f / r1;
        const int row0 = b * NTOK + TTXT + q0 + wrow + mt * 16 + g;
        const int row1 = row0 + 8;
        #pragma unroll
        for (int nt = 0; nt < 8; nt++) {
            const int c = h * HD + nt * 8 + tg * 2;
            uint32_t hp, lp;
            pack_hilo(O[mt][nt][0] * inv0, O[mt][nt][1] * inv0, hp, lp);
            *(uint32_t*)(gaoc + (size_t)row0 * KC + c)       = hp;
            *(uint32_t*)(gaoc + (size_t)row0 * KC + 768 + c) = lp;
            pack_hilo(O[mt][nt][2] * inv1, O[mt][nt][3] * inv1, hp, lp);
            *(uint32_t*)(gaoc + (size_t)row1 * KC + c)       = hp;
            *(uint32_t*)(gaoc + (size_t)row1 * KC + 768 + c) = lp;
        }
    }
}

// ---------------- launch ----------------
extern "C" void kernel_launch(void* const* d_in, const int* in_sizes, int n_in,
                              void* d_out, int out_size)
{
    const float* x      = (const float*)d_in[0];
    const float* qkv_w  = (const float*)d_in[1];
    const float* proj_w = (const float*)d_in[2];
    const float* proj_b = (const float*)d_in[3];
    float* out = (float*)d_out;

    cudaFuncSetAttribute(img_attn_mma_kernel,
                         cudaFuncAttributeMaxDynamicSharedMemorySize, IMG_SMEM2);
    cudaFuncSetAttribute(qkv_gemm_kernel,
                         cudaFuncAttributeMaxDynamicSharedMemorySize, GEMM_SMEM);
    cudaFuncSetAttribute(proj_gemm_kernel,
                         cudaFuncAttributeMaxDynamicSharedMemorySize, GEMM_SMEM);

    split_x_kernel<<<(MPAD*(CDIM/2) + 255)/256, 256>>>(x);
    split_w_kernel<<<((NQKV+CDIM)*(CDIM/2) + 255)/256, 256>>>(qkv_w, proj_w);

    qkv_gemm_kernel<<<dim3(NQKV/128, MPAD/128), 128, GEMM_SMEM>>>();

    text_attn_kernel<<<B_*H_, 64>>>();
    img_attn_mma_kernel<<<dim3(SIMG/128, B_*H_), 128, IMG_SMEM2>>>();

    proj_gemm_kernel<<<dim3(CDIM/128, MPAD/128), 128, GEMM_SMEM>>>(proj_b, out);
}

// round 15
// speedup vs baseline: 1.4837x; 1.0367x over previous
#include <cuda_runtime.h>
#include <cuda_bf16.h>
#include <cstdint>

// ---------------- problem constants ----------------
#define B_    8
#define TTXT  40
#define SIMG  1024
#define NTOK  1064
#define CDIM  768
#define H_    12
#define HD    64
#define MROWS (B_*NTOK)       // 8512
#define MPAD  8576            // 67*128
#define KC    (2*CDIM)        // 1536 : compact [hi|lo] K length
#define NQKV  (3*CDIM)        // 2304

// ---------------- device scratch (referenced ONLY from device code) ----------------
__device__ __align__(16) __nv_bfloat16 gxc [MPAD*KC];
__device__ __align__(16) __nv_bfloat16 gw1c[NQKV*KC];
__device__ __align__(16) __nv_bfloat16 gw2c[CDIM*KC];
__device__ __align__(16) __nv_bfloat16 gaoc[MPAD*KC];

__device__ __align__(16) __nv_bfloat16 g_qc [B_*H_*NTOK*128];  // [bh][n][hi64|lo64]
__device__ __align__(16) __nv_bfloat16 g_kc [B_*H_*NTOK*128];  // [bh][n][hi64|lo64]
__device__ __align__(16) __nv_bfloat16 g_vht[B_*H_*HD*NTOK];   // V^T hi: [bh][e][n]
__device__ __align__(16) __nv_bfloat16 g_vlt[B_*H_*HD*NTOK];   // V^T lo

// ---------------- helpers ----------------
__device__ __forceinline__ void pack_hilo(float x, float y, uint32_t& hi, uint32_t& lo)
{
    __nv_bfloat162 h = __floats2bfloat162_rn(x, y);
    float hx = __bfloat162float(h.x), hy = __bfloat162float(h.y);
    __nv_bfloat162 l = __floats2bfloat162_rn(x - hx, y - hy);
    hi = *(uint32_t*)&h;
    lo = *(uint32_t*)&l;
}

// ---------------- split kernels ----------------
__global__ __launch_bounds__(256) void split_x_kernel(const float* __restrict__ src)
{
    int i = blockIdx.x * 256 + threadIdx.x;
    if (i >= MPAD * (CDIM/2)) return;
    int row = i / (CDIM/2), c = (i - row * (CDIM/2)) * 2;
    float f0 = 0.f, f1 = 0.f;
    if (row < MROWS) {
        float2 v = *(const float2*)(src + (size_t)row * CDIM + c);
        f0 = v.x; f1 = v.y;
    }
    uint32_t hp, lp;
    pack_hilo(f0, f1, hp, lp);
    *(uint32_t*)(gxc + (size_t)row * KC + c)       = hp;
    *(uint32_t*)(gxc + (size_t)row * KC + 768 + c) = lp;
}

__global__ __launch_bounds__(256) void split_w_kernel(const float* __restrict__ w1,
                                                      const float* __restrict__ w2)
{
    int i = blockIdx.x * 256 + threadIdx.x;
    if (i >= (NQKV + CDIM) * (CDIM/2)) return;
    int row = i / (CDIM/2), c = (i - row * (CDIM/2)) * 2;
    const float* src;
    __nv_bfloat16* dst;
    int r;
    if (row < NQKV) { src = w1; dst = gw1c; r = row; }
    else            { src = w2; dst = gw2c; r = row - NQKV; }
    float2 v = *(const float2*)(src + (size_t)r * CDIM + c);
    uint32_t hp, lp;
    pack_hilo(v.x, v.y, hp, lp);
    *(uint32_t*)(dst + (size_t)r * KC + c)       = hp;
    *(uint32_t*)(dst + (size_t)r * KC + 768 + c) = lp;
}

// ---------------- warp mma + ldmatrix + cp.async ----------------
__device__ __forceinline__ void mma16816(float* d, const uint32_t* a, const uint32_t* b)
{
    asm volatile(
        "mma.sync.aligned.m16n8k16.row.col.f32.bf16.bf16.f32 "
        "{%0,%1,%2,%3}, {%4,%5,%6,%7}, {%8,%9}, {%0,%1,%2,%3};"
        : "+f"(d[0]), "+f"(d[1]), "+f"(d[2]), "+f"(d[3])
        : "r"(a[0]), "r"(a[1]), "r"(a[2]), "r"(a[3]), "r"(b[0]), "r"(b[1]));
}

__device__ __forceinline__ void ldsm4(uint32_t* r, uint32_t addr)
{
    asm volatile("ldmatrix.sync.aligned.m8n8.x4.shared.b16 {%0,%1,%2,%3}, [%4];"
        : "=r"(r[0]), "=r"(r[1]), "=r"(r[2]), "=r"(r[3]) : "r"(addr));
}

__device__ __forceinline__ void cpa16(uint32_t dst, const void* src)
{
    asm volatile("cp.async.cg.shared.global [%0], [%1], 16;" :: "r"(dst), "l"(src));
}
#define CP_COMMIT() asm volatile("cp.async.commit_group;" ::: "memory")
#define CP_WAIT(n)  asm volatile("cp.async.wait_group %0;" :: "n"(n) : "memory")

// D[128,128], 3-term split GEMM, term-grouped (round-14 validated).
#define CSTG  10240
#define GSTG  (4*CSTG)
#define GEMM_SMEM (2*GSTG)           // 81920

__device__ __forceinline__ void gemm_main(const __nv_bfloat16* __restrict__ A,
                                          const __nv_bfloat16* __restrict__ B,
                                          int m0, int n0, float acc[4][8][4],
                                          char* gsm)
{
    const int tid  = threadIdx.x;
    const int lane = tid & 31, wid = tid >> 5;
    const int wm = (wid & 1) * 64;
    const int wn = (wid >> 1) * 64;

    const int lr = tid >> 2;
    const int lkb = (tid & 3) * 16;

    const uint32_t sm0 = (uint32_t)__cvta_generic_to_shared(gsm);

    const char* Ap = (const char*)(A + (size_t)(m0 + lr) * KC) + lkb;
    const char* Bp = (const char*)(B + (size_t)(n0 + lr) * KC) + lkb;

    const uint32_t d0 = sm0 + lr * 80 + lkb;

    const uint32_t aOff = ((wm + (lane & 15)) * 80 + (lane >> 4) * 16);
    const uint32_t bOff = ((wn + ((lane >> 4) * 8) + (lane & 7)) * 80
                           + ((lane >> 3) & 1) * 16);

    const int NKI = 24;

    auto load_chunk = [&](int c, int s) {
        const uint32_t base = d0 + s * GSTG;
        const size_t oh = (size_t)c * 64;
        const size_t ol = 1536 + (size_t)c * 64;
        #pragma unroll
        for (int i = 0; i < 4; i++) {
            const size_t rs = (size_t)(32*i) * KC * 2;
            cpa16(base            + (32*i) * 80, Ap + oh + rs);
            cpa16(base + CSTG     + (32*i) * 80, Ap + ol + rs);
            cpa16(base + 2*CSTG   + (32*i) * 80, Bp + oh + rs);
            cpa16(base + 3*CSTG   + (32*i) * 80, Bp + ol + rs);
        }
        CP_COMMIT();
    };

    load_chunk(0, 0);

    for (int t = 0; t < NKI; t++) {
        CP_WAIT(0);
        __syncthreads();
        if (t + 1 < NKI) load_chunk(t + 1, (t + 1) & 1);

        const uint32_t sb = sm0 + (t & 1) * GSTG;
        #pragma unroll
        for (int ks = 0; ks < 2; ks++) {
            const uint32_t ko = ks * 32;
            uint32_t ah[4][4], al[4][4], bh[8][2], bl[8][2];
            #pragma unroll
            for (int mt = 0; mt < 4; mt++)
                ldsm4(ah[mt], sb + aOff + mt * (16 * 80) + ko);
            #pragma unroll
            for (int np = 0; np < 4; np++) {
                uint32_t tmp[4];
                ldsm4(tmp, sb + 2*CSTG + bOff + np * (16 * 80) + ko);
                bh[2*np][0] = tmp[0]; bh[2*np][1] = tmp[1];
                bh[2*np+1][0] = tmp[2]; bh[2*np+1][1] = tmp[3];
            }
            #pragma unroll
            for (int mt = 0; mt < 4; mt++)
                #pragma unroll
                for (int nt = 0; nt < 8; nt++)
                    mma16816(acc[mt][nt], ah[mt], bh[nt]);

            #pragma unroll
            for (int np = 0; np < 4; np++) {
                uint32_t tmp[4];
                ldsm4(tmp, sb + 3*CSTG + bOff + np * (16 * 80) + ko);
                bl[2*np][0] = tmp[0]; bl[2*np][1] = tmp[1];
                bl[2*np+1][0] = tmp[2]; bl[2*np+1][1] = tmp[3];
            }
            #pragma unroll
            for (int mt = 0; mt < 4; mt++)
                #pragma unroll
                for (int nt = 0; nt < 8; nt++)
                    mma16816(acc[mt][nt], ah[mt], bl[nt]);

            #pragma unroll
            for (int mt = 0; mt < 4; mt++)
                ldsm4(al[mt], sb + CSTG + aOff + mt * (16 * 80) + ko);
            #pragma unroll
            for (int mt = 0; mt < 4; mt++)
                #pragma unroll
                for (int nt = 0; nt < 8; nt++)
                    mma16816(acc[mt][nt], al[mt], bh[nt]);
        }
    }
}

// ---------------- QKV GEMM: epilogue writes attention-ready layouts ----------------
__global__ __launch_bounds__(128) void qkv_gemm_kernel()
{
    extern __shared__ char gsm[];
    const int n0 = blockIdx.x * 128;
    const int m0 = blockIdx.y * 128;

    float acc[4][8][4] = {};
    gemm_main(gxc, gw1c, m0, n0, acc, gsm);

    const int lane = threadIdx.x & 31, wid = threadIdx.x >> 5;
    const int wm = (wid & 1) * 64, wn = (wid >> 1) * 64;
    const int g = lane >> 2, tg = lane & 3;

    const int s3    = n0 / CDIM;
    const int nrem0 = n0 - s3 * CDIM;

    #pragma unroll
    for (int mt = 0; mt < 4; mt++) {
        #pragma unroll
        for (int nt = 0; nt < 8; nt++) {
            const int col = nrem0 + wn + nt * 8 + tg * 2;
            const int hh = col >> 6, e = col & 63;
            #pragma unroll
            for (int rr = 0; rr < 2; rr++) {
                const int mm = m0 + wm + mt * 16 + g + rr * 8;
                if (mm >= MROWS) continue;
                const int b = mm / NTOK;
                const int n = mm - b * NTOK;
                const size_t idx = (size_t)(b * H_ + hh) * NTOK + n;
                uint32_t hp, lp;
                pack_hilo(acc[mt][nt][rr * 2 + 0], acc[mt][nt][rr * 2 + 1], hp, lp);
                if (s3 == 0) {
                    *(uint32_t*)(g_qc + idx * 128 + e)      = hp;
                    *(uint32_t*)(g_qc + idx * 128 + 64 + e) = lp;
                } else if (s3 == 1) {
                    *(uint32_t*)(g_kc + idx * 128 + e)      = hp;
                    *(uint32_t*)(g_kc + idx * 128 + 64 + e) = lp;
                } else {
                    const __nv_bfloat162 h2 = *(__nv_bfloat162*)&hp;
                    const __nv_bfloat162 l2 = *(__nv_bfloat162*)&lp;
                    const size_t vi = ((size_t)(b * H_ + hh) * HD + e) * NTOK + n;
                    g_vht[vi]        = h2.x;
                    g_vht[vi + NTOK] = h2.y;
                    g_vlt[vi]        = l2.x;
                    g_vlt[vi + NTOK] = l2.y;
                }
            }
        }
    }
}

// ---------------- proj GEMM kernel ----------------
__global__ __launch_bounds__(128) void proj_gemm_kernel(const float* __restrict__ bias,
                                                        float* __restrict__ out)
{
    extern __shared__ char gsm[];
    const int n0 = blockIdx.x * 128;
    const int m0 = blockIdx.y * 128;

    float acc[4][8][4] = {};
    gemm_main(gaoc, gw2c, m0, n0, acc, gsm);

    const int lane = threadIdx.x & 31, wid = threadIdx.x >> 5;
    const int wm = (wid & 1) * 64, wn = (wid >> 1) * 64;
    const int g = lane >> 2, tg = lane & 3;

    #pragma unroll
    for (int mt = 0; mt < 4; mt++) {
        #pragma unroll
        for (int nt = 0; nt < 8; nt++) {
            const int d = n0 + wn + nt * 8 + tg * 2;
            const float b0 = bias[d], b1 = bias[d + 1];
            #pragma unroll
            for (int rr = 0; rr < 2; rr++) {
                const int m = m0 + wm + mt * 16 + g + rr * 8;
                if (m >= MROWS) continue;
                out[(size_t)m * CDIM + d]     = acc[mt][nt][rr * 2 + 0] + b0;
                out[(size_t)m * CDIM + d + 1] = acc[mt][nt][rr * 2 + 1] + b1;
            }
        }
    }
}

// ---------------- unified attention: mma flash kernel ----------------
// grid (9, 96): bx<8 -> image blocks (128 queries, 17 key tiles, keylim NTOK);
//               bx==8 -> text block (queries = tokens 0..127, only first 40
//                        stored, 1 key tile, keylim TTXT).
// fixed-max softmax (M=20): p = exp(s*0.125 - 20).
#define QP     136
#define VPITCH 72
#define OFF_K  34816
#define OFF_VH 52224
#define VSTG   9216
#define OFF_VL (OFF_VH + 2*VSTG)     // 70656
#define IMG_SMEM2 (OFF_VL + 2*VSTG)  // 89088
#define SMAX   20.0f

__global__ __launch_bounds__(128) void attn_mma_kernel()
{
    extern __shared__ char smx[];
    __nv_bfloat16* Qs = (__nv_bfloat16*)(smx);            // [128][136]
    __nv_bfloat16* Ks = (__nv_bfloat16*)(smx + OFF_K);    // [64][136]

    const int bh = blockIdx.y;
    const bool istext = (blockIdx.x == 8);
    const int qtok   = istext ? 0 : TTXT + blockIdx.x * 128;   // first query token
    const int ntiles = istext ? 1 : 17;
    const int keylim = istext ? TTXT : NTOK;

    const int tid = threadIdx.x;
    const int lane = tid & 31, wid = tid >> 5;
    const int g = lane >> 2, tg = lane & 3;
    const int wrow = wid * 32;

    const uint32_t qAddr = (uint32_t)__cvta_generic_to_shared(Qs);
    const uint32_t ksAddr = (uint32_t)__cvta_generic_to_shared(Ks);
    const uint32_t vhAddr = (uint32_t)__cvta_generic_to_shared(smx + OFF_VH);
    const uint32_t vlAddr = (uint32_t)__cvta_generic_to_shared(smx + OFF_VL);

    const uint32_t qBase = qAddr
        + ((wrow + (lane & 15)) * QP + (lane >> 4) * 8) * 2;
    const uint32_t kBase = ksAddr
        + ((((lane >> 4) * 8) + (lane & 7)) * QP + ((lane >> 3) & 1) * 8) * 2;
    const uint32_t vfragOff =
        ((((lane >> 4) * 8) + (lane & 7)) * VPITCH + ((lane >> 3) & 1) * 8) * 2;

    const __nv_bfloat16* qcb = g_qc + ((size_t)bh * NTOK + qtok) * 128;
    const __nv_bfloat16* kcb = g_kc + (size_t)bh * NTOK * 128;
    const __nv_bfloat16* vhb = g_vht + (size_t)bh * HD * NTOK;
    const __nv_bfloat16* vlb = g_vlt + (size_t)bh * HD * NTOK;

    auto load_k = [&](int jj) {
        for (int u = tid; u < 64 * 16; u += 128) {
            int r = u >> 4, o = (u & 15) * 8;
            if (jj + r < NTOK)
                cpa16(ksAddr + (r * QP + o) * 2, kcb + (size_t)(jj + r) * 128 + o);
            else
                *(uint4*)&Ks[r * QP + o] = make_uint4(0u, 0u, 0u, 0u);
        }
    };
    auto load_v = [&](int jj, int stg) {
        const uint32_t vhD = vhAddr + stg * VSTG;
        const uint32_t vlD = vlAddr + stg * VSTG;
        __nv_bfloat16* VhP = (__nv_bfloat16*)(smx + OFF_VH + stg * VSTG);
        __nv_bfloat16* VlP = (__nv_bfloat16*)(smx + OFF_VL + stg * VSTG);
        for (int u = tid; u < 64 * 8; u += 128) {
            int e = u >> 3, o = (u & 7) * 8;
            if (jj + o + 7 < NTOK) {
                cpa16(vhD + (e * VPITCH + o) * 2, vhb + (size_t)e * NTOK + jj + o);
                cpa16(vlD + (e * VPITCH + o) * 2, vlb + (size_t)e * NTOK + jj + o);
            } else {
                *(uint4*)&VhP[e * VPITCH + o] = make_uint4(0u, 0u, 0u, 0u);
                *(uint4*)&VlP[e * VPITCH + o] = make_uint4(0u, 0u, 0u, 0u);
            }
        }
    };

    // prologue
    for (int u = tid; u < 128 * 16; u += 128) {
        int r = u >> 4, o = (u & 15) * 8;
        cpa16(qAddr + (r * QP + o) * 2, qcb + (size_t)r * 128 + o);
    }
    load_k(0);
    load_v(0, 0);
    CP_COMMIT();

    float lsum[2][2] = {{0.f, 0.f}, {0.f, 0.f}};
    float O[2][8][4];
    #pragma unroll
    for (int mt = 0; mt < 2; mt++)
        #pragma unroll
        for (int nt = 0; nt < 8; nt++)
            #pragma unroll
            for (int j = 0; j < 4; j++) O[mt][nt][j] = 0.f;

    for (int t = 0; t < ntiles; t++) {
        const int j0 = t * 64;
        CP_WAIT(0);
        __syncthreads();

        // ---- scores ----
        float S[2][8][4];
        #pragma unroll
        for (int mt = 0; mt < 2; mt++)
            #pragma unroll
            for (int nt = 0; nt < 8; nt++)
                #pragma unroll
                for (int j = 0; j < 4; j++) S[mt][nt][j] = 0.f;

        #pragma unroll
        for (int ks = 0; ks < 12; ks++) {
            const int qc = (ks < 8) ? (ks & 3) : (ks - 4);
            const int kc = (ks < 8) ? ks : (ks - 8);
            uint32_t a[2][4];
            ldsm4(a[0], qBase + qc * 32);
            ldsm4(a[1], qBase + 16 * (QP * 2) + qc * 32);
            uint32_t bfr[8][2];
            #pragma unroll
            for (int np = 0; np < 4; np++) {
                uint32_t tmp[4];
                ldsm4(tmp, kBase + np * (16 * QP * 2) + kc * 32);
                bfr[2*np][0]   = tmp[0];
                bfr[2*np][1]   = tmp[1];
                bfr[2*np+1][0] = tmp[2];
                bfr[2*np+1][1] = tmp[3];
            }
            #pragma unroll
            for (int nt = 0; nt < 8; nt++) {
                mma16816(S[0][nt], a[0], bfr[nt]);
                mma16816(S[1][nt], a[1], bfr[nt]);
            }
        }

        // prefetch next K/V
        __syncthreads();
        if (t + 1 < ntiles) {
            load_k(j0 + 64);
            load_v(j0 + 64, (t + 1) & 1);
            CP_COMMIT();
        }

        // ---- fixed-max softmax ----
        #pragma unroll
        for (int mt = 0; mt < 2; mt++) {
            #pragma unroll
            for (int nt = 0; nt < 8; nt++) {
                const int key = j0 + nt * 8 + tg * 2;
                const bool v0 = key < keylim, v1 = key + 1 < keylim;
                S[mt][nt][0] = v0 ? __expf(fmaf(S[mt][nt][0], 0.125f, -SMAX)) : 0.f;
                S[mt][nt][1] = v1 ? __expf(fmaf(S[mt][nt][1], 0.125f, -SMAX)) : 0.f;
                S[mt][nt][2] = v0 ? __expf(fmaf(S[mt][nt][2], 0.125f, -SMAX)) : 0.f;
                S[mt][nt][3] = v1 ? __expf(fmaf(S[mt][nt][3], 0.125f, -SMAX)) : 0.f;
                lsum[mt][0] += S[mt][nt][0] + S[mt][nt][1];
                lsum[mt][1] += S[mt][nt][2] + S[mt][nt][3];
            }
        }

        // pack P into A-fragments (hi + lo)
        uint32_t ph[2][4][4], pl[2][4][4];
        #pragma unroll
        for (int mt = 0; mt < 2; mt++) {
            #pragma unroll
            for (int ks = 0; ks < 4; ks++) {
                pack_hilo(S[mt][2*ks][0],   S[mt][2*ks][1],   ph[mt][ks][0], pl[mt][ks][0]);
                pack_hilo(S[mt][2*ks][2],   S[mt][2*ks][3],   ph[mt][ks][1], pl[mt][ks][1]);
                pack_hilo(S[mt][2*ks+1][0], S[mt][2*ks+1][1], ph[mt][ks][2], pl[mt][ks][2]);
                pack_hilo(S[mt][2*ks+1][2], S[mt][2*ks+1][3], ph[mt][ks][3], pl[mt][ks][3]);
            }
        }

        // ---- PV ----
        const uint32_t vhBase = vhAddr + (t & 1) * VSTG + vfragOff;
        const uint32_t vlBase = vlAddr + (t & 1) * VSTG + vfragOff;
        #pragma unroll
        for (int ks = 0; ks < 4; ks++) {
            uint32_t vh2[8][2], vl2[8][2];
            #pragma unroll
            for (int np = 0; np < 4; np++) {
                uint32_t th[4], tl[4];
                ldsm4(th, vhBase + np * (16 * VPITCH * 2) + ks * 32);
                ldsm4(tl, vlBase + np * (16 * VPITCH * 2) + ks * 32);
                vh2[2*np][0] = th[0]; vh2[2*np][1] = th[1];
                vh2[2*np+1][0] = th[2]; vh2[2*np+1][1] = th[3];
                vl2[2*np][0] = tl[0]; vl2[2*np][1] = tl[1];
                vl2[2*np+1][0] = tl[2]; vl2[2*np+1][1] = tl[3];
            }
            #pragma unroll
            for (int nt = 0; nt < 8; nt++) {
                #pragma unroll
                for (int mt = 0; mt < 2; mt++) {
                    mma16816(O[mt][nt], ph[mt][ks], vh2[nt]);
                    mma16816(O[mt][nt], ph[mt][ks], vl2[nt]);
                    mma16816(O[mt][nt], pl[mt][ks], vh2[nt]);
                }
            }
        }
    }

    // final row-sum reduction + epilogue (compact packed stores)
    const int b = bh / H_, h = bh - b * H_;
    #pragma unroll
    for (int mt = 0; mt < 2; mt++) {
        float r0 = lsum[mt][0], r1 = lsum[mt][1];
        r0 += __shfl_xor_sync(0xffffffffu, r0, 1);
        r0 += __shfl_xor_sync(0xffffffffu, r0, 2);
        r1 += __shfl_xor_sync(0xffffffffu, r1, 1);
        r1 += __shfl_xor_sync(0xffffffffu, r1, 2);
        const float inv0 = 1.f / r0, inv1 = 1.f / r1;
        const int rq0 = wrow + mt * 16 + g;       // query row within block
        const int rq1 = rq0 + 8;
        const int row0 = b * NTOK + qtok + rq0;
        const int row1 = row0 + 8;
        const bool st0 = !istext || (rq0 < TTXT);
        const bool st1 = !istext || (rq1 < TTXT);
        #pragma unroll
        for (int nt = 0; nt < 8; nt++) {
            const int c = h * HD + nt * 8 + tg * 2;
            uint32_t hp, lp;
            if (st0) {
                pack_hilo(O[mt][nt][0] * inv0, O[mt][nt][1] * inv0, hp, lp);
                *(uint32_t*)(gaoc + (size_t)row0 * KC + c)       = hp;
                *(uint32_t*)(gaoc + (size_t)row0 * KC + 768 + c) = lp;
            }
            if (st1) {
                pack_hilo(O[mt][nt][2] * inv1, O[mt][nt][3] * inv1, hp, lp);
                *(uint32_t*)(gaoc + (size_t)row1 * KC + c)       = hp;
                *(uint32_t*)(gaoc + (size_t)row1 * KC + 768 + c) = lp;
            }
        }
    }
}

// ---------------- launch ----------------
extern "C" void kernel_launch(void* const* d_in, const int* in_sizes, int n_in,
                              void* d_out, int out_size)
{
    const float* x      = (const float*)d_in[0];
    const float* qkv_w  = (const float*)d_in[1];
    const float* proj_w = (const float*)d_in[2];
    const float* proj_b = (const float*)d_in[3];
    float* out = (float*)d_out;

    cudaFuncSetAttribute(attn_mma_kernel,
                         cudaFuncAttributeMaxDynamicSharedMemorySize, IMG_SMEM2);
    cudaFuncSetAttribute(qkv_gemm_kernel,
                         cudaFuncAttributeMaxDynamicSharedMemorySize, GEMM_SMEM);
    cudaFuncSetAttribute(proj_gemm_kernel,
                         cudaFuncAttributeMaxDynamicSharedMemorySize, GEMM_SMEM);

    split_x_kernel<<<(MPAD*(CDIM/2) + 255)/256, 256>>>(x);
    split_w_kernel<<<((NQKV+CDIM)*(CDIM/2) + 255)/256, 256>>>(qkv_w, proj_w);

    qkv_gemm_kernel<<<dim3(NQKV/128, MPAD/128), 128, GEMM_SMEM>>>();

    attn_mma_kernel<<<dim3(9, B_*H_), 128, IMG_SMEM2>>>();

    proj_gemm_kernel<<<dim3(CDIM/128, MPAD/128), 128, GEMM_SMEM>>>(proj_b, out);
}